// round 5
// baseline (speedup 1.0000x reference)
#include <cuda_runtime.h>
#include <cstddef>
#include <cstdint>

#define Bn 8
#define Cc 256
#define Nn 4096      // 64*64 spatial
#define Mm 1024      // 32*32 pooled
#define Dd 32
#define Dv 128

// Scratch (device globals; no allocations allowed)
__device__ float g_theta[Bn * Nn * Dd];   // (n, i, d)
__device__ float g_phi[Bn * Dd * Mm];     // (n, d, j)
__device__ float g_gp [Bn * Dv * Mm];     // (n, v, j)

__device__ __forceinline__ void mma_tf32(float c[4], const uint32_t a[4],
                                         uint32_t b0, uint32_t b1) {
    asm volatile("mma.sync.aligned.m16n8k8.row.col.f32.tf32.tf32.f32 "
        "{%0,%1,%2,%3}, {%4,%5,%6,%7}, {%8,%9}, {%0,%1,%2,%3};"
        : "+f"(c[0]), "+f"(c[1]), "+f"(c[2]), "+f"(c[3])
        : "r"(a[0]), "r"(a[1]), "r"(a[2]), "r"(a[3]), "r"(b0), "r"(b1));
}
__device__ __forceinline__ void cp16(void* dst_smem, const void* src) {
    uint32_t d = (uint32_t)__cvta_generic_to_shared(dst_smem);
    asm volatile("cp.async.cg.shared.global [%0], [%1], 16;\n" :: "r"(d), "l"(src));
}
__device__ __forceinline__ void cp_commit() {
    asm volatile("cp.async.commit_group;\n");
}
template<int N> __device__ __forceinline__ void cp_wait() {
    asm volatile("cp.async.wait_group %0;\n" :: "n"(N));
}

// ---------------------------------------------------------------------------
// Kernel 1: fused projections + maxpool, tf32 MMA, cp.async double-buffered.
// Ys epilogue buffer ALIASES the pipeline buffers (smem 85->53 KB, occ up).
// grid (32 i-tiles, 3 groups, 8 batches), 256 threads = 8 warps (4m x 2n).
// ---------------------------------------------------------------------------
#define WS  36    // weight smem stride (A frag banks 4*gq+tq, conflict-free)
#define XSS 136   // X smem stride      (B frag banks 8*tq+gq, conflict-free)
#define YSS 132

__global__ void __launch_bounds__(256) proj_mma_kernel(
    const float* __restrict__ x,
    const float* __restrict__ theta_w, const float* __restrict__ theta_b,
    const float* __restrict__ phi_w,   const float* __restrict__ phi_b,
    const float* __restrict__ g_w,     const float* __restrict__ g_b)
{
    extern __shared__ float sm[];
    float* Ws = sm;                    // 2 x 64 x 36
    float* Xs = sm + 2 * 64 * WS;      // 2 x 32 x 136
    float* Ys = sm;                    // 64 x 132 (aliases pipeline, used after)

    const int bi  = blockIdx.x;
    const int grp = blockIdx.y;
    const int n   = blockIdx.z;
    const int t   = threadIdx.x;
    const int w   = t >> 5, lane = t & 31;
    const int gq  = lane >> 2, tq = lane & 3;
    const int mrow = (w & 3) * 16;
    const int nc0  = (w >> 2) * 64;
    const int base = bi * 128;

    const float* xb = x + (size_t)n * Cc * Nn;

    auto issue = [&](int kc, int buf) {
        float* Wb = Ws + buf * 64 * WS;
        float* Xb = Xs + buf * 32 * XSS;
#pragma unroll
        for (int it = 0; it < 2; it++) {
            int idx = t + it * 256;             // W: 64x32 -> 512 cp16
            int r = idx >> 3, kq = (idx & 7) * 4;
            const float* src;
            if (grp == 0) src = (r < 32) ? &theta_w[r * Cc + kc + kq]
                                         : &phi_w[(r - 32) * Cc + kc + kq];
            else          src = &g_w[((grp - 1) * 64 + r) * Cc + kc + kq];
            cp16(&Wb[r * WS + kq], src);
        }
#pragma unroll
        for (int it = 0; it < 4; it++) {
            int idx = t + it * 256;             // X: 32x128 -> 1024 cp16
            int k = idx >> 5, i4 = (idx & 31) * 4;
            cp16(&Xb[k * XSS + i4], &xb[(size_t)(kc + k) * Nn + base + i4]);
        }
        cp_commit();
    };

    float acc[8][4];
#pragma unroll
    for (int nt = 0; nt < 8; nt++)
#pragma unroll
        for (int c = 0; c < 4; c++) acc[nt][c] = 0.f;

    issue(0, 0);
    for (int c8 = 0; c8 < 8; c8++) {
        if (c8 < 7) { issue((c8 + 1) * 32, (c8 + 1) & 1); cp_wait<1>(); }
        else        { cp_wait<0>(); }
        __syncthreads();
        const float* Wb = Ws + (c8 & 1) * 64 * WS;
        const float* Xb = Xs + (c8 & 1) * 32 * XSS;
#pragma unroll
        for (int ks = 0; ks < 4; ks++) {
            uint32_t a[4];
            a[0] = __float_as_uint(Wb[(mrow + gq    ) * WS + ks * 8 + tq    ]);
            a[1] = __float_as_uint(Wb[(mrow + gq + 8) * WS + ks * 8 + tq    ]);
            a[2] = __float_as_uint(Wb[(mrow + gq    ) * WS + ks * 8 + tq + 4]);
            a[3] = __float_as_uint(Wb[(mrow + gq + 8) * WS + ks * 8 + tq + 4]);
#pragma unroll
            for (int nt = 0; nt < 8; nt++) {
                uint32_t b0 = __float_as_uint(Xb[(ks * 8 + tq    ) * XSS + nc0 + nt * 8 + gq]);
                uint32_t b1 = __float_as_uint(Xb[(ks * 8 + tq + 4) * XSS + nc0 + nt * 8 + gq]);
                mma_tf32(acc[nt], a, b0, b1);
            }
        }
        __syncthreads();   // last sync also guards the Ys aliasing below
    }

    // stage to Ys (aliases pipeline smem; safe after trailing sync)
    {
        int r0 = mrow + gq, r1 = mrow + gq + 8;
        float b0, b1;
        if (grp == 0) {
            b0 = (r0 < 32) ? theta_b[r0] : phi_b[r0 - 32];
            b1 = (r1 < 32) ? theta_b[r1] : phi_b[r1 - 32];
        } else {
            b0 = g_b[(grp - 1) * 64 + r0];
            b1 = g_b[(grp - 1) * 64 + r1];
        }
#pragma unroll
        for (int nt = 0; nt < 8; nt++) {
            int col = nc0 + nt * 8 + tq * 2;
            *(float2*)&Ys[r0 * YSS + col] = make_float2(acc[nt][0] + b0, acc[nt][1] + b0);
            *(float2*)&Ys[r1 * YSS + col] = make_float2(acc[nt][2] + b1, acc[nt][3] + b1);
        }
    }
    __syncthreads();

    if (grp == 0) {
        for (int idx = t; idx < 32 * 128; idx += 256) {
            int o = idx & 31, i = idx >> 5;
            g_theta[((size_t)n * Nn + base + i) * Dd + o] = Ys[o * YSS + i];
        }
        for (int idx = t; idx < 32 * 32; idx += 256) {
            int o = idx >> 5, jw = idx & 31;
            const float* yr = &Ys[(32 + o) * YSS];
            float m0 = fmaxf(yr[2 * jw],      yr[2 * jw + 1]);
            float m1 = fmaxf(yr[64 + 2 * jw], yr[64 + 2 * jw + 1]);
            g_phi[((size_t)n * Dd + o) * Mm + bi * 32 + jw] = fmaxf(m0, m1);
        }
    } else {
        int vbase = (grp - 1) * 64;
        for (int idx = t; idx < 64 * 32; idx += 256) {
            int v = idx >> 5, jw = idx & 31;
            const float* yr = &Ys[v * YSS];
            float m0 = fmaxf(yr[2 * jw],      yr[2 * jw + 1]);
            float m1 = fmaxf(yr[64 + 2 * jw], yr[64 + 2 * jw + 1]);
            g_gp[((size_t)n * Dv + vbase + v) * Mm + bi * 32 + jw] = fmaxf(m0, m1);
        }
    }
}

// ---------------------------------------------------------------------------
// Kernel 2: FUSED flash attention + output conv + residual.
// Phase 1: flash attention (tf32 MMA, cp.async double-buffer, shuffle P).
// Phase 2: stage normalized O[128q x 128v] to smem (aliases pipeline bufs).
// Phase 3: out[c,i] = gamma*(W.O + b) + x, 4 passes of 64 channels.
// grid (32 q-tiles, 8 batches), 256 threads = 8 warps.
// ---------------------------------------------------------------------------
#define KB  64
#define PHS 72   // phi stride
#define GSS 68   // g   stride
#define ASS 132  // O   stride [i][v] (B frag banks 4*gq+tq conflict-free)
#define OWS 132  // out_w stride      (A frag banks 4*gq+tq conflict-free)

__global__ void __launch_bounds__(256) attn_fused_kernel(
    const float* __restrict__ x,
    const float* __restrict__ out_w,
    const float* __restrict__ out_b,
    const float* __restrict__ gamma,
    float* __restrict__ out)
{
    extern __shared__ float sm[];
    // phase 1 layout
    float* Phs = sm;                     // 2 x 32 x 72
    float* Gs  = sm + 2 * Dd * PHS;      // 2 x 128 x 68
    // phase 2/3 layout (aliases phase 1)
    float* As  = sm;                     // 128 x 132
    float* Wsm = sm + 128 * ASS;         // 64 x 132

    const int n  = blockIdx.y;
    const int i0 = blockIdx.x * 128;
    const int t  = threadIdx.x;
    const int w  = t >> 5;
    const int lane = t & 31;
    const int qb = w * 16;
    const int gq = lane >> 2;
    const int tq = lane & 3;

    // Q A-fragments (persist)
    uint32_t qa[4][4];
    {
        const float* th = g_theta + ((size_t)n * Nn + i0 + qb) * Dd;
#pragma unroll
        for (int kc = 0; kc < 4; kc++) {
            qa[kc][0] = __float_as_uint(th[(gq    ) * Dd + kc * 8 + tq    ]);
            qa[kc][1] = __float_as_uint(th[(gq + 8) * Dd + kc * 8 + tq    ]);
            qa[kc][2] = __float_as_uint(th[(gq    ) * Dd + kc * 8 + tq + 4]);
            qa[kc][3] = __float_as_uint(th[(gq + 8) * Dd + kc * 8 + tq + 4]);
        }
    }

    auto issue = [&](int jb, int buf) {
        float* Pb = Phs + buf * Dd * PHS;
        float* Gb = Gs  + buf * Dv * GSS;
#pragma unroll
        for (int it = 0; it < 2; it++) {
            int idx = t + it * 256;
            int d = idx >> 4, j4 = (idx & 15) * 4;
            cp16(&Pb[d * PHS + j4], &g_phi[((size_t)n * Dd + d) * Mm + jb + j4]);
        }
#pragma unroll
        for (int it = 0; it < 8; it++) {
            int idx = t + it * 256;
            int vv = idx >> 4, j4 = (idx & 15) * 4;
            cp16(&Gb[vv * GSS + j4], &g_gp[((size_t)n * Dv + vv) * Mm + jb + j4]);
        }
        cp_commit();
    };

    float oacc[16][4];
#pragma unroll
    for (int vt = 0; vt < 16; vt++)
#pragma unroll
        for (int c = 0; c < 4; c++) oacc[vt][c] = 0.f;

    float m0 = -1e30f, m1 = -1e30f, l0 = 0.f, l1 = 0.f;

    issue(0, 0);
    for (int kb = 0; kb < Mm / KB; kb++) {
        if (kb < Mm / KB - 1) { issue((kb + 1) * KB, (kb + 1) & 1); cp_wait<1>(); }
        else                  { cp_wait<0>(); }
        __syncthreads();
        const float* Pb = Phs + (kb & 1) * Dd * PHS;
        const float* Gb = Gs  + (kb & 1) * Dv * GSS;

        float e[8][4];
#pragma unroll
        for (int nt = 0; nt < 8; nt++)
#pragma unroll
            for (int c = 0; c < 4; c++) e[nt][c] = 0.f;
#pragma unroll
        for (int kc = 0; kc < 4; kc++)
#pragma unroll
            for (int nt = 0; nt < 8; nt++) {
                uint32_t b0 = __float_as_uint(Pb[(kc * 8 + tq    ) * PHS + nt * 8 + gq]);
                uint32_t b1 = __float_as_uint(Pb[(kc * 8 + tq + 4) * PHS + nt * 8 + gq]);
                mma_tf32(e[nt], qa[kc], b0, b1);
            }

        float rm0 = m0, rm1 = m1;
#pragma unroll
        for (int nt = 0; nt < 8; nt++) {
            rm0 = fmaxf(rm0, fmaxf(e[nt][0], e[nt][1]));
            rm1 = fmaxf(rm1, fmaxf(e[nt][2], e[nt][3]));
        }
        rm0 = fmaxf(rm0, __shfl_xor_sync(0xffffffff, rm0, 1));
        rm0 = fmaxf(rm0, __shfl_xor_sync(0xffffffff, rm0, 2));
        rm1 = fmaxf(rm1, __shfl_xor_sync(0xffffffff, rm1, 1));
        rm1 = fmaxf(rm1, __shfl_xor_sync(0xffffffff, rm1, 2));
        float sc0 = __expf(m0 - rm0);
        float sc1 = __expf(m1 - rm1);
        m0 = rm0; m1 = rm1;

        float s0 = 0.f, s1 = 0.f;
#pragma unroll
        for (int nt = 0; nt < 8; nt++) {
            e[nt][0] = __expf(e[nt][0] - rm0);
            e[nt][1] = __expf(e[nt][1] - rm0);
            e[nt][2] = __expf(e[nt][2] - rm1);
            e[nt][3] = __expf(e[nt][3] - rm1);
            s0 += e[nt][0] + e[nt][1];
            s1 += e[nt][2] + e[nt][3];
        }
        s0 += __shfl_xor_sync(0xffffffff, s0, 1);
        s0 += __shfl_xor_sync(0xffffffff, s0, 2);
        s1 += __shfl_xor_sync(0xffffffff, s1, 1);
        s1 += __shfl_xor_sync(0xffffffff, s1, 2);
        l0 = l0 * sc0 + s0;
        l1 = l1 * sc1 + s1;

#pragma unroll
        for (int vt = 0; vt < 16; vt++) {
            oacc[vt][0] *= sc0; oacc[vt][1] *= sc0;
            oacc[vt][2] *= sc1; oacc[vt][3] *= sc1;
        }

        const int parity = tq & 1;
        const int s_lo = tq >> 1;
#pragma unroll
        for (int kc = 0; kc < 8; kc++) {
            float v0 = __shfl_sync(0xffffffff, e[kc][0], s_lo,     4);
            float v1 = __shfl_sync(0xffffffff, e[kc][1], s_lo,     4);
            float v2 = __shfl_sync(0xffffffff, e[kc][2], s_lo,     4);
            float v3 = __shfl_sync(0xffffffff, e[kc][3], s_lo,     4);
            float w0 = __shfl_sync(0xffffffff, e[kc][0], s_lo + 2, 4);
            float w1 = __shfl_sync(0xffffffff, e[kc][1], s_lo + 2, 4);
            float w2 = __shfl_sync(0xffffffff, e[kc][2], s_lo + 2, 4);
            float w3 = __shfl_sync(0xffffffff, e[kc][3], s_lo + 2, 4);
            uint32_t pa[4];
            pa[0] = __float_as_uint(parity ? v1 : v0);
            pa[1] = __float_as_uint(parity ? v3 : v2);
            pa[2] = __float_as_uint(parity ? w1 : w0);
            pa[3] = __float_as_uint(parity ? w3 : w2);
#pragma unroll
            for (int vt = 0; vt < 16; vt++) {
                uint32_t b0 = __float_as_uint(Gb[(vt * 8 + gq) * GSS + kc * 8 + tq    ]);
                uint32_t b1 = __float_as_uint(Gb[(vt * 8 + gq) * GSS + kc * 8 + tq + 4]);
                mma_tf32(oacc[vt], pa, b0, b1);
            }
        }
        __syncthreads();   // all reads of this buffer done (also guards phase 2)
    }

    // ---- phase 2: stage normalized O to smem (aliases pipeline buffers) ----
    // issue pass-0 weights first so they overlap the O stores
#pragma unroll
    for (int it = 0; it < 8; it++) {
        int idx = t + it * 256;                  // 64 x 128 -> 2048 cp16
        int r = idx >> 5, v4 = (idx & 31) * 4;
        cp16(&Wsm[r * OWS + v4], &out_w[(size_t)r * Dv + v4]);
    }
    cp_commit();

    {
        const float inv0 = 1.f / l0;
        const float inv1 = 1.f / l1;
        float* r0p = &As[(qb + gq    ) * ASS];
        float* r1p = &As[(qb + gq + 8) * ASS];
#pragma unroll
        for (int vt = 0; vt < 16; vt++) {
            *(float2*)&r0p[vt * 8 + tq * 2] = make_float2(oacc[vt][0] * inv0, oacc[vt][1] * inv0);
            *(float2*)&r1p[vt * 8 + tq * 2] = make_float2(oacc[vt][2] * inv1, oacc[vt][3] * inv1);
        }
    }
    cp_wait<0>();
    __syncthreads();

    // ---- phase 3: out conv, 4 passes of 64 channels ----
    const float gm = gamma[0];
    const int mrow = (w & 3) * 16;
    const int nc0  = (w >> 2) * 64;

    for (int pass = 0; pass < 4; pass++) {
        const int cbase = pass * 64;

        float acc[8][4];
#pragma unroll
        for (int nt = 0; nt < 8; nt++)
#pragma unroll
            for (int c = 0; c < 4; c++) acc[nt][c] = 0.f;

#pragma unroll
        for (int kc = 0; kc < 16; kc++) {
            uint32_t a[4];
            a[0] = __float_as_uint(Wsm[(mrow + gq    ) * OWS + kc * 8 + tq    ]);
            a[1] = __float_as_uint(Wsm[(mrow + gq + 8) * OWS + kc * 8 + tq    ]);
            a[2] = __float_as_uint(Wsm[(mrow + gq    ) * OWS + kc * 8 + tq + 4]);
            a[3] = __float_as_uint(Wsm[(mrow + gq + 8) * OWS + kc * 8 + tq + 4]);
#pragma unroll
            for (int nt = 0; nt < 8; nt++) {
                uint32_t b0 = __float_as_uint(As[(nc0 + nt * 8 + gq) * ASS + kc * 8 + tq    ]);
                uint32_t b1 = __float_as_uint(As[(nc0 + nt * 8 + gq) * ASS + kc * 8 + tq + 4]);
                mma_tf32(acc[nt], a, b0, b1);
            }
        }

        const int c0 = cbase + mrow + gq;
        const int c1 = c0 + 8;
        const float b0 = out_b[c0], b1 = out_b[c1];
#pragma unroll
        for (int nt = 0; nt < 8; nt++) {
            int col = i0 + nc0 + nt * 8 + tq * 2;
            size_t off0 = ((size_t)n * Cc + c0) * Nn + col;
            size_t off1 = ((size_t)n * Cc + c1) * Nn + col;
            float2 xv0 = *(const float2*)&x[off0];
            float2 xv1 = *(const float2*)&x[off1];
            float2 o0, o1;
            o0.x = gm * (acc[nt][0] + b0) + xv0.x;
            o0.y = gm * (acc[nt][1] + b0) + xv0.y;
            o1.x = gm * (acc[nt][2] + b1) + xv1.x;
            o1.y = gm * (acc[nt][3] + b1) + xv1.y;
            *(float2*)&out[off0] = o0;
            *(float2*)&out[off1] = o1;
        }

        if (pass < 3) {
            __syncthreads();   // all reads of Wsm done before refill
#pragma unroll
            for (int it = 0; it < 8; it++) {
                int idx = t + it * 256;
                int r = idx >> 5, v4 = (idx & 31) * 4;
                cp16(&Wsm[r * OWS + v4], &out_w[(size_t)(cbase + 64 + r) * Dv + v4]);
            }
            cp_commit();
            cp_wait<0>();
            __syncthreads();
        }
    }
}

// ---------------------------------------------------------------------------
extern "C" void kernel_launch(void* const* d_in, const int* in_sizes, int n_in,
                              void* d_out, int out_size)
{
    const float* x       = (const float*)d_in[0];
    const float* theta_w = (const float*)d_in[1];
    const float* theta_b = (const float*)d_in[2];
    const float* phi_w   = (const float*)d_in[3];
    const float* phi_b   = (const float*)d_in[4];
    const float* g_w     = (const float*)d_in[5];
    const float* g_b     = (const float*)d_in[6];
    const float* out_w   = (const float*)d_in[7];
    const float* out_b   = (const float*)d_in[8];
    const float* gamma   = (const float*)d_in[9];
    float* out = (float*)d_out;

    // proj: pipeline (2*64*36 + 2*32*136 = 13312 floats) aliased with Ys(8448)
    const int smem1 = 13312 * 4;                                   // 53 KB
    // fused: max(phase1 22016, phase2/3 128*132+64*132=25344) floats
    const int smem2 = 25344 * 4;                                   // ~101 KB

    cudaFuncSetAttribute(proj_mma_kernel,   cudaFuncAttributeMaxDynamicSharedMemorySize, smem1);
    cudaFuncSetAttribute(attn_fused_kernel, cudaFuncAttributeMaxDynamicSharedMemorySize, smem2);

    proj_mma_kernel<<<dim3(32, 3, Bn), 256, smem1>>>(x, theta_w, theta_b,
                                                     phi_w, phi_b, g_w, g_b);
    attn_fused_kernel<<<dim3(32, Bn), 256, smem2>>>(x, out_w, out_b, gamma, out);
}

// round 6
// speedup vs baseline: 1.1011x; 1.1011x over previous
#include <cuda_runtime.h>
#include <cstddef>
#include <cstdint>

#define Bn 8
#define Cc 256
#define Nn 4096      // 64*64 spatial
#define Mm 1024      // 32*32 pooled
#define Dd 32
#define Dv 128

// Scratch (device globals; no allocations allowed)
__device__ float g_theta[Bn * Nn * Dd];   // (n, i, d)
__device__ float g_phi[Bn * Dd * Mm];     // (n, d, j)
__device__ float g_gp [Bn * Dv * Mm];     // (n, v, j)

__device__ __forceinline__ void mma_tf32(float c[4], const uint32_t a[4],
                                         uint32_t b0, uint32_t b1) {
    asm volatile("mma.sync.aligned.m16n8k8.row.col.f32.tf32.tf32.f32 "
        "{%0,%1,%2,%3}, {%4,%5,%6,%7}, {%8,%9}, {%0,%1,%2,%3};"
        : "+f"(c[0]), "+f"(c[1]), "+f"(c[2]), "+f"(c[3])
        : "r"(a[0]), "r"(a[1]), "r"(a[2]), "r"(a[3]), "r"(b0), "r"(b1));
}
__device__ __forceinline__ void cp16(void* dst_smem, const void* src) {
    uint32_t d = (uint32_t)__cvta_generic_to_shared(dst_smem);
    asm volatile("cp.async.cg.shared.global [%0], [%1], 16;\n" :: "r"(d), "l"(src));
}
__device__ __forceinline__ void cp_commit() {
    asm volatile("cp.async.commit_group;\n");
}
template<int N> __device__ __forceinline__ void cp_wait() {
    asm volatile("cp.async.wait_group %0;\n" :: "n"(N));
}

// ---------------------------------------------------------------------------
// Kernel 1: fused projections + maxpool, tf32 MMA, cp.async double-buffered.
// grid (32 i-tiles, 3 groups, 8 batches), 256 threads = 8 warps (4m x 2n).
// ---------------------------------------------------------------------------
#define WS  36    // weight smem stride (A frag banks 4*gq+tq, conflict-free)
#define XSS 136   // X smem stride      (B frag banks 8*tq+gq, conflict-free)
#define YSS 132

__global__ void __launch_bounds__(256, 3) proj_mma_kernel(
    const float* __restrict__ x,
    const float* __restrict__ theta_w, const float* __restrict__ theta_b,
    const float* __restrict__ phi_w,   const float* __restrict__ phi_b,
    const float* __restrict__ g_w,     const float* __restrict__ g_b)
{
    extern __shared__ float sm[];
    float* Ws = sm;                    // 2 x 64 x 36
    float* Xs = sm + 2 * 64 * WS;      // 2 x 32 x 136
    float* Ys = sm;                    // 64 x 132 (aliases pipeline, used after)

    const int bi  = blockIdx.x;
    const int grp = blockIdx.y;
    const int n   = blockIdx.z;
    const int t   = threadIdx.x;
    const int w   = t >> 5, lane = t & 31;
    const int gq  = lane >> 2, tq = lane & 3;
    const int mrow = (w & 3) * 16;
    const int nc0  = (w >> 2) * 64;
    const int base = bi * 128;

    const float* xb = x + (size_t)n * Cc * Nn;

    auto issue = [&](int kc, int buf) {
        float* Wb = Ws + buf * 64 * WS;
        float* Xb = Xs + buf * 32 * XSS;
#pragma unroll
        for (int it = 0; it < 2; it++) {
            int idx = t + it * 256;             // W: 64x32 -> 512 cp16
            int r = idx >> 3, kq = (idx & 7) * 4;
            const float* src;
            if (grp == 0) src = (r < 32) ? &theta_w[r * Cc + kc + kq]
                                         : &phi_w[(r - 32) * Cc + kc + kq];
            else          src = &g_w[((grp - 1) * 64 + r) * Cc + kc + kq];
            cp16(&Wb[r * WS + kq], src);
        }
#pragma unroll
        for (int it = 0; it < 4; it++) {
            int idx = t + it * 256;             // X: 32x128 -> 1024 cp16
            int k = idx >> 5, i4 = (idx & 31) * 4;
            cp16(&Xb[k * XSS + i4], &xb[(size_t)(kc + k) * Nn + base + i4]);
        }
        cp_commit();
    };

    float acc[8][4];
#pragma unroll
    for (int nt = 0; nt < 8; nt++)
#pragma unroll
        for (int c = 0; c < 4; c++) acc[nt][c] = 0.f;

    issue(0, 0);
    for (int c8 = 0; c8 < 8; c8++) {
        if (c8 < 7) { issue((c8 + 1) * 32, (c8 + 1) & 1); cp_wait<1>(); }
        else        { cp_wait<0>(); }
        __syncthreads();
        const float* Wb = Ws + (c8 & 1) * 64 * WS;
        const float* Xb = Xs + (c8 & 1) * 32 * XSS;
#pragma unroll
        for (int ks = 0; ks < 4; ks++) {
            uint32_t a[4];
            a[0] = __float_as_uint(Wb[(mrow + gq    ) * WS + ks * 8 + tq    ]);
            a[1] = __float_as_uint(Wb[(mrow + gq + 8) * WS + ks * 8 + tq    ]);
            a[2] = __float_as_uint(Wb[(mrow + gq    ) * WS + ks * 8 + tq + 4]);
            a[3] = __float_as_uint(Wb[(mrow + gq + 8) * WS + ks * 8 + tq + 4]);
#pragma unroll
            for (int nt = 0; nt < 8; nt++) {
                uint32_t b0 = __float_as_uint(Xb[(ks * 8 + tq    ) * XSS + nc0 + nt * 8 + gq]);
                uint32_t b1 = __float_as_uint(Xb[(ks * 8 + tq + 4) * XSS + nc0 + nt * 8 + gq]);
                mma_tf32(acc[nt], a, b0, b1);
            }
        }
        __syncthreads();   // last sync also guards the Ys aliasing below
    }

    // stage to Ys (aliases pipeline smem; safe after trailing sync)
    {
        int r0 = mrow + gq, r1 = mrow + gq + 8;
        float b0, b1;
        if (grp == 0) {
            b0 = (r0 < 32) ? theta_b[r0] : phi_b[r0 - 32];
            b1 = (r1 < 32) ? theta_b[r1] : phi_b[r1 - 32];
        } else {
            b0 = g_b[(grp - 1) * 64 + r0];
            b1 = g_b[(grp - 1) * 64 + r1];
        }
#pragma unroll
        for (int nt = 0; nt < 8; nt++) {
            int col = nc0 + nt * 8 + tq * 2;
            *(float2*)&Ys[r0 * YSS + col] = make_float2(acc[nt][0] + b0, acc[nt][1] + b0);
            *(float2*)&Ys[r1 * YSS + col] = make_float2(acc[nt][2] + b1, acc[nt][3] + b1);
        }
    }
    __syncthreads();

    if (grp == 0) {
        for (int idx = t; idx < 32 * 128; idx += 256) {
            int o = idx & 31, i = idx >> 5;
            g_theta[((size_t)n * Nn + base + i) * Dd + o] = Ys[o * YSS + i];
        }
        for (int idx = t; idx < 32 * 32; idx += 256) {
            int o = idx >> 5, jw = idx & 31;
            const float* yr = &Ys[(32 + o) * YSS];
            float m0 = fmaxf(yr[2 * jw],      yr[2 * jw + 1]);
            float m1 = fmaxf(yr[64 + 2 * jw], yr[64 + 2 * jw + 1]);
            g_phi[((size_t)n * Dd + o) * Mm + bi * 32 + jw] = fmaxf(m0, m1);
        }
    } else {
        int vbase = (grp - 1) * 64;
        for (int idx = t; idx < 64 * 32; idx += 256) {
            int v = idx >> 5, jw = idx & 31;
            const float* yr = &Ys[v * YSS];
            float m0 = fmaxf(yr[2 * jw],      yr[2 * jw + 1]);
            float m1 = fmaxf(yr[64 + 2 * jw], yr[64 + 2 * jw + 1]);
            g_gp[((size_t)n * Dv + vbase + v) * Mm + bi * 32 + jw] = fmaxf(m0, m1);
        }
    }
}

// ---------------------------------------------------------------------------
// Kernel 2: FUSED flash attention + output conv + residual.
// __launch_bounds__(256, 2): cap regs at 128 -> 2 blocks/SM -> single wave
// (grid 256 <= 296 slots). This is the R5->R6 occupancy fix.
// ---------------------------------------------------------------------------
#define KB  64
#define PHS 72   // phi stride
#define GSS 68   // g   stride
#define ASS 132  // O   stride [i][v] (B frag banks 4*gq+tq conflict-free)
#define OWS 132  // out_w stride      (A frag banks 4*gq+tq conflict-free)

__global__ void __launch_bounds__(256, 2) attn_fused_kernel(
    const float* __restrict__ x,
    const float* __restrict__ out_w,
    const float* __restrict__ out_b,
    const float* __restrict__ gamma,
    float* __restrict__ out)
{
    extern __shared__ float sm[];
    // phase 1 layout
    float* Phs = sm;                     // 2 x 32 x 72
    float* Gs  = sm + 2 * Dd * PHS;      // 2 x 128 x 68
    // phase 2/3 layout (aliases phase 1)
    float* As  = sm;                     // 128 x 132
    float* Wsm = sm + 128 * ASS;         // 64 x 132

    const int n  = blockIdx.y;
    const int i0 = blockIdx.x * 128;
    const int t  = threadIdx.x;
    const int w  = t >> 5;
    const int lane = t & 31;
    const int qb = w * 16;
    const int gq = lane >> 2;
    const int tq = lane & 3;

    // Q A-fragments (persist)
    uint32_t qa[4][4];
    {
        const float* th = g_theta + ((size_t)n * Nn + i0 + qb) * Dd;
#pragma unroll
        for (int kc = 0; kc < 4; kc++) {
            qa[kc][0] = __float_as_uint(th[(gq    ) * Dd + kc * 8 + tq    ]);
            qa[kc][1] = __float_as_uint(th[(gq + 8) * Dd + kc * 8 + tq    ]);
            qa[kc][2] = __float_as_uint(th[(gq    ) * Dd + kc * 8 + tq + 4]);
            qa[kc][3] = __float_as_uint(th[(gq + 8) * Dd + kc * 8 + tq + 4]);
        }
    }

    auto issue = [&](int jb, int buf) {
        float* Pb = Phs + buf * Dd * PHS;
        float* Gb = Gs  + buf * Dv * GSS;
#pragma unroll
        for (int it = 0; it < 2; it++) {
            int idx = t + it * 256;
            int d = idx >> 4, j4 = (idx & 15) * 4;
            cp16(&Pb[d * PHS + j4], &g_phi[((size_t)n * Dd + d) * Mm + jb + j4]);
        }
#pragma unroll
        for (int it = 0; it < 8; it++) {
            int idx = t + it * 256;
            int vv = idx >> 4, j4 = (idx & 15) * 4;
            cp16(&Gb[vv * GSS + j4], &g_gp[((size_t)n * Dv + vv) * Mm + jb + j4]);
        }
        cp_commit();
    };

    float oacc[16][4];
#pragma unroll
    for (int vt = 0; vt < 16; vt++)
#pragma unroll
        for (int c = 0; c < 4; c++) oacc[vt][c] = 0.f;

    float m0 = -1e30f, m1 = -1e30f, l0 = 0.f, l1 = 0.f;

    issue(0, 0);
    for (int kb = 0; kb < Mm / KB; kb++) {
        if (kb < Mm / KB - 1) { issue((kb + 1) * KB, (kb + 1) & 1); cp_wait<1>(); }
        else                  { cp_wait<0>(); }
        __syncthreads();
        const float* Pb = Phs + (kb & 1) * Dd * PHS;
        const float* Gb = Gs  + (kb & 1) * Dv * GSS;

        float e[8][4];
#pragma unroll
        for (int nt = 0; nt < 8; nt++)
#pragma unroll
            for (int c = 0; c < 4; c++) e[nt][c] = 0.f;
#pragma unroll
        for (int kc = 0; kc < 4; kc++)
#pragma unroll
            for (int nt = 0; nt < 8; nt++) {
                uint32_t b0 = __float_as_uint(Pb[(kc * 8 + tq    ) * PHS + nt * 8 + gq]);
                uint32_t b1 = __float_as_uint(Pb[(kc * 8 + tq + 4) * PHS + nt * 8 + gq]);
                mma_tf32(e[nt], qa[kc], b0, b1);
            }

        float rm0 = m0, rm1 = m1;
#pragma unroll
        for (int nt = 0; nt < 8; nt++) {
            rm0 = fmaxf(rm0, fmaxf(e[nt][0], e[nt][1]));
            rm1 = fmaxf(rm1, fmaxf(e[nt][2], e[nt][3]));
        }
        rm0 = fmaxf(rm0, __shfl_xor_sync(0xffffffff, rm0, 1));
        rm0 = fmaxf(rm0, __shfl_xor_sync(0xffffffff, rm0, 2));
        rm1 = fmaxf(rm1, __shfl_xor_sync(0xffffffff, rm1, 1));
        rm1 = fmaxf(rm1, __shfl_xor_sync(0xffffffff, rm1, 2));
        float sc0 = __expf(m0 - rm0);
        float sc1 = __expf(m1 - rm1);
        m0 = rm0; m1 = rm1;

        float s0 = 0.f, s1 = 0.f;
#pragma unroll
        for (int nt = 0; nt < 8; nt++) {
            e[nt][0] = __expf(e[nt][0] - rm0);
            e[nt][1] = __expf(e[nt][1] - rm0);
            e[nt][2] = __expf(e[nt][2] - rm1);
            e[nt][3] = __expf(e[nt][3] - rm1);
            s0 += e[nt][0] + e[nt][1];
            s1 += e[nt][2] + e[nt][3];
        }
        s0 += __shfl_xor_sync(0xffffffff, s0, 1);
        s0 += __shfl_xor_sync(0xffffffff, s0, 2);
        s1 += __shfl_xor_sync(0xffffffff, s1, 1);
        s1 += __shfl_xor_sync(0xffffffff, s1, 2);
        l0 = l0 * sc0 + s0;
        l1 = l1 * sc1 + s1;

#pragma unroll
        for (int vt = 0; vt < 16; vt++) {
            oacc[vt][0] *= sc0; oacc[vt][1] *= sc0;
            oacc[vt][2] *= sc1; oacc[vt][3] *= sc1;
        }

        const int parity = tq & 1;
        const int s_lo = tq >> 1;
#pragma unroll
        for (int kc = 0; kc < 8; kc++) {
            float v0 = __shfl_sync(0xffffffff, e[kc][0], s_lo,     4);
            float v1 = __shfl_sync(0xffffffff, e[kc][1], s_lo,     4);
            float v2 = __shfl_sync(0xffffffff, e[kc][2], s_lo,     4);
            float v3 = __shfl_sync(0xffffffff, e[kc][3], s_lo,     4);
            float w0 = __shfl_sync(0xffffffff, e[kc][0], s_lo + 2, 4);
            float w1 = __shfl_sync(0xffffffff, e[kc][1], s_lo + 2, 4);
            float w2 = __shfl_sync(0xffffffff, e[kc][2], s_lo + 2, 4);
            float w3 = __shfl_sync(0xffffffff, e[kc][3], s_lo + 2, 4);
            uint32_t pa[4];
            pa[0] = __float_as_uint(parity ? v1 : v0);
            pa[1] = __float_as_uint(parity ? v3 : v2);
            pa[2] = __float_as_uint(parity ? w1 : w0);
            pa[3] = __float_as_uint(parity ? w3 : w2);
#pragma unroll
            for (int vt = 0; vt < 16; vt++) {
                uint32_t b0 = __float_as_uint(Gb[(vt * 8 + gq) * GSS + kc * 8 + tq    ]);
                uint32_t b1 = __float_as_uint(Gb[(vt * 8 + gq) * GSS + kc * 8 + tq + 4]);
                mma_tf32(oacc[vt], pa, b0, b1);
            }
        }
        __syncthreads();   // all reads of this buffer done (also guards phase 2)
    }

    // ---- phase 2: stage normalized O to smem (aliases pipeline buffers) ----
#pragma unroll
    for (int it = 0; it < 8; it++) {
        int idx = t + it * 256;                  // 64 x 128 -> 2048 cp16
        int r = idx >> 5, v4 = (idx & 31) * 4;
        cp16(&Wsm[r * OWS + v4], &out_w[(size_t)r * Dv + v4]);
    }
    cp_commit();

    {
        const float inv0 = 1.f / l0;
        const float inv1 = 1.f / l1;
        float* r0p = &As[(qb + gq    ) * ASS];
        float* r1p = &As[(qb + gq + 8) * ASS];
#pragma unroll
        for (int vt = 0; vt < 16; vt++) {
            *(float2*)&r0p[vt * 8 + tq * 2] = make_float2(oacc[vt][0] * inv0, oacc[vt][1] * inv0);
            *(float2*)&r1p[vt * 8 + tq * 2] = make_float2(oacc[vt][2] * inv1, oacc[vt][3] * inv1);
        }
    }
    cp_wait<0>();
    __syncthreads();

    // ---- phase 3: out conv, 4 passes of 64 channels ----
    const float gm = gamma[0];
    const int mrow = (w & 3) * 16;
    const int nc0  = (w >> 2) * 64;

    for (int pass = 0; pass < 4; pass++) {
        const int cbase = pass * 64;

        float acc[8][4];
#pragma unroll
        for (int nt = 0; nt < 8; nt++)
#pragma unroll
            for (int c = 0; c < 4; c++) acc[nt][c] = 0.f;

#pragma unroll
        for (int kc = 0; kc < 16; kc++) {
            uint32_t a[4];
            a[0] = __float_as_uint(Wsm[(mrow + gq    ) * OWS + kc * 8 + tq    ]);
            a[1] = __float_as_uint(Wsm[(mrow + gq + 8) * OWS + kc * 8 + tq    ]);
            a[2] = __float_as_uint(Wsm[(mrow + gq    ) * OWS + kc * 8 + tq + 4]);
            a[3] = __float_as_uint(Wsm[(mrow + gq + 8) * OWS + kc * 8 + tq + 4]);
#pragma unroll
            for (int nt = 0; nt < 8; nt++) {
                uint32_t b0 = __float_as_uint(As[(nc0 + nt * 8 + gq) * ASS + kc * 8 + tq    ]);
                uint32_t b1 = __float_as_uint(As[(nc0 + nt * 8 + gq) * ASS + kc * 8 + tq + 4]);
                mma_tf32(acc[nt], a, b0, b1);
            }
        }

        const int c0 = cbase + mrow + gq;
        const int c1 = c0 + 8;
        const float b0 = out_b[c0], b1 = out_b[c1];
#pragma unroll
        for (int nt = 0; nt < 8; nt++) {
            int col = i0 + nc0 + nt * 8 + tq * 2;
            size_t off0 = ((size_t)n * Cc + c0) * Nn + col;
            size_t off1 = ((size_t)n * Cc + c1) * Nn + col;
            float2 xv0 = *(const float2*)&x[off0];
            float2 xv1 = *(const float2*)&x[off1];
            float2 o0, o1;
            o0.x = gm * (acc[nt][0] + b0) + xv0.x;
            o0.y = gm * (acc[nt][1] + b0) + xv0.y;
            o1.x = gm * (acc[nt][2] + b1) + xv1.x;
            o1.y = gm * (acc[nt][3] + b1) + xv1.y;
            *(float2*)&out[off0] = o0;
            *(float2*)&out[off1] = o1;
        }

        if (pass < 3) {
            __syncthreads();   // all reads of Wsm done before refill
#pragma unroll
            for (int it = 0; it < 8; it++) {
                int idx = t + it * 256;
                int r = idx >> 5, v4 = (idx & 31) * 4;
                cp16(&Wsm[r * OWS + v4], &out_w[(size_t)(cbase + 64 + r) * Dv + v4]);
            }
            cp_commit();
            cp_wait<0>();
            __syncthreads();
        }
    }
}

// ---------------------------------------------------------------------------
extern "C" void kernel_launch(void* const* d_in, const int* in_sizes, int n_in,
                              void* d_out, int out_size)
{
    const float* x       = (const float*)d_in[0];
    const float* theta_w = (const float*)d_in[1];
    const float* theta_b = (const float*)d_in[2];
    const float* phi_w   = (const float*)d_in[3];
    const float* phi_b   = (const float*)d_in[4];
    const float* g_w     = (const float*)d_in[5];
    const float* g_b     = (const float*)d_in[6];
    const float* out_w   = (const float*)d_in[7];
    const float* out_b   = (const float*)d_in[8];
    const float* gamma   = (const float*)d_in[9];
    float* out = (float*)d_out;

    const int smem1 = 13312 * 4;   // 53 KB (pipeline aliased with Ys)
    const int smem2 = 25344 * 4;   // ~101 KB (phase1 22016 fl < phase2/3 25344 fl)

    cudaFuncSetAttribute(proj_mma_kernel,   cudaFuncAttributeMaxDynamicSharedMemorySize, smem1);
    cudaFuncSetAttribute(attn_fused_kernel, cudaFuncAttributeMaxDynamicSharedMemorySize, smem2);

    proj_mma_kernel<<<dim3(32, 3, Bn), 256, smem1>>>(x, theta_w, theta_b,
                                                     phi_w, phi_b, g_w, g_b);
    attn_fused_kernel<<<dim3(32, Bn), 256, smem2>>>(x, out_w, out_b, gamma, out);
}

// round 7
// speedup vs baseline: 1.5994x; 1.4526x over previous
#include <cuda_runtime.h>
#include <cuda_bf16.h>
#include <cstddef>
#include <cstdint>

#define Bn 8
#define Cc 256
#define Nn 4096      // 64*64 spatial
#define Mm 1024      // 32*32 pooled
#define Dd 32
#define Dv 128

// Scratch (device globals; no allocations allowed)
__device__ float          g_theta[Bn * Nn * Dd];   // (n, i, d) fp32
__device__ float          g_phi  [Bn * Dd * Mm];   // (n, d, j) fp32
__device__ __nv_bfloat16  g_gp   [Bn * Dv * Mm];   // (n, v, j) bf16

__device__ __forceinline__ void mma_tf32(float c[4], const uint32_t a[4],
                                         uint32_t b0, uint32_t b1) {
    asm volatile("mma.sync.aligned.m16n8k8.row.col.f32.tf32.tf32.f32 "
        "{%0,%1,%2,%3}, {%4,%5,%6,%7}, {%8,%9}, {%0,%1,%2,%3};"
        : "+f"(c[0]), "+f"(c[1]), "+f"(c[2]), "+f"(c[3])
        : "r"(a[0]), "r"(a[1]), "r"(a[2]), "r"(a[3]), "r"(b0), "r"(b1));
}
__device__ __forceinline__ void mma_bf16(float c[4], const uint32_t a[4],
                                         uint32_t b0, uint32_t b1) {
    asm volatile("mma.sync.aligned.m16n8k16.row.col.f32.bf16.bf16.f32 "
        "{%0,%1,%2,%3}, {%4,%5,%6,%7}, {%8,%9}, {%0,%1,%2,%3};"
        : "+f"(c[0]), "+f"(c[1]), "+f"(c[2]), "+f"(c[3])
        : "r"(a[0]), "r"(a[1]), "r"(a[2]), "r"(a[3]), "r"(b0), "r"(b1));
}
__device__ __forceinline__ uint32_t pkbf(float lo, float hi) {
    uint32_t r;
    asm("cvt.rn.bf16x2.f32 %0, %1, %2;" : "=r"(r) : "f"(hi), "f"(lo));
    return r;
}
__device__ __forceinline__ void cp16(void* dst_smem, const void* src) {
    uint32_t d = (uint32_t)__cvta_generic_to_shared(dst_smem);
    asm volatile("cp.async.cg.shared.global [%0], [%1], 16;\n" :: "r"(d), "l"(src));
}
__device__ __forceinline__ void cp_commit() {
    asm volatile("cp.async.commit_group;\n");
}
template<int N> __device__ __forceinline__ void cp_wait() {
    asm volatile("cp.async.wait_group %0;\n" :: "n"(N));
}

// ---------------------------------------------------------------------------
// Kernel 1: fused projections + maxpool, tf32 MMA, cp.async double-buffered.
// g_gp now written as bf16. grid (32, 3, 8), 256 threads.
// ---------------------------------------------------------------------------
#define WS  36
#define XSS 136
#define YSS 132

__global__ void __launch_bounds__(256, 3) proj_mma_kernel(
    const float* __restrict__ x,
    const float* __restrict__ theta_w, const float* __restrict__ theta_b,
    const float* __restrict__ phi_w,   const float* __restrict__ phi_b,
    const float* __restrict__ g_w,     const float* __restrict__ g_b)
{
    extern __shared__ float sm[];
    float* Ws = sm;                    // 2 x 64 x 36
    float* Xs = sm + 2 * 64 * WS;      // 2 x 32 x 136
    float* Ys = sm;                    // 64 x 132 (aliases pipeline)

    const int bi  = blockIdx.x;
    const int grp = blockIdx.y;
    const int n   = blockIdx.z;
    const int t   = threadIdx.x;
    const int w   = t >> 5, lane = t & 31;
    const int gq  = lane >> 2, tq = lane & 3;
    const int mrow = (w & 3) * 16;
    const int nc0  = (w >> 2) * 64;
    const int base = bi * 128;

    const float* xb = x + (size_t)n * Cc * Nn;

    auto issue = [&](int kc, int buf) {
        float* Wb = Ws + buf * 64 * WS;
        float* Xb = Xs + buf * 32 * XSS;
#pragma unroll
        for (int it = 0; it < 2; it++) {
            int idx = t + it * 256;
            int r = idx >> 3, kq = (idx & 7) * 4;
            const float* src;
            if (grp == 0) src = (r < 32) ? &theta_w[r * Cc + kc + kq]
                                         : &phi_w[(r - 32) * Cc + kc + kq];
            else          src = &g_w[((grp - 1) * 64 + r) * Cc + kc + kq];
            cp16(&Wb[r * WS + kq], src);
        }
#pragma unroll
        for (int it = 0; it < 4; it++) {
            int idx = t + it * 256;
            int k = idx >> 5, i4 = (idx & 31) * 4;
            cp16(&Xb[k * XSS + i4], &xb[(size_t)(kc + k) * Nn + base + i4]);
        }
        cp_commit();
    };

    float acc[8][4];
#pragma unroll
    for (int nt = 0; nt < 8; nt++)
#pragma unroll
        for (int c = 0; c < 4; c++) acc[nt][c] = 0.f;

    issue(0, 0);
    for (int c8 = 0; c8 < 8; c8++) {
        if (c8 < 7) { issue((c8 + 1) * 32, (c8 + 1) & 1); cp_wait<1>(); }
        else        { cp_wait<0>(); }
        __syncthreads();
        const float* Wb = Ws + (c8 & 1) * 64 * WS;
        const float* Xb = Xs + (c8 & 1) * 32 * XSS;
#pragma unroll
        for (int ks = 0; ks < 4; ks++) {
            uint32_t a[4];
            a[0] = __float_as_uint(Wb[(mrow + gq    ) * WS + ks * 8 + tq    ]);
            a[1] = __float_as_uint(Wb[(mrow + gq + 8) * WS + ks * 8 + tq    ]);
            a[2] = __float_as_uint(Wb[(mrow + gq    ) * WS + ks * 8 + tq + 4]);
            a[3] = __float_as_uint(Wb[(mrow + gq + 8) * WS + ks * 8 + tq + 4]);
#pragma unroll
            for (int nt = 0; nt < 8; nt++) {
                uint32_t b0 = __float_as_uint(Xb[(ks * 8 + tq    ) * XSS + nc0 + nt * 8 + gq]);
                uint32_t b1 = __float_as_uint(Xb[(ks * 8 + tq + 4) * XSS + nc0 + nt * 8 + gq]);
                mma_tf32(acc[nt], a, b0, b1);
            }
        }
        __syncthreads();
    }

    {
        int r0 = mrow + gq, r1 = mrow + gq + 8;
        float b0, b1;
        if (grp == 0) {
            b0 = (r0 < 32) ? theta_b[r0] : phi_b[r0 - 32];
            b1 = (r1 < 32) ? theta_b[r1] : phi_b[r1 - 32];
        } else {
            b0 = g_b[(grp - 1) * 64 + r0];
            b1 = g_b[(grp - 1) * 64 + r1];
        }
#pragma unroll
        for (int nt = 0; nt < 8; nt++) {
            int col = nc0 + nt * 8 + tq * 2;
            *(float2*)&Ys[r0 * YSS + col] = make_float2(acc[nt][0] + b0, acc[nt][1] + b0);
            *(float2*)&Ys[r1 * YSS + col] = make_float2(acc[nt][2] + b1, acc[nt][3] + b1);
        }
    }
    __syncthreads();

    if (grp == 0) {
        for (int idx = t; idx < 32 * 128; idx += 256) {
            int o = idx & 31, i = idx >> 5;
            g_theta[((size_t)n * Nn + base + i) * Dd + o] = Ys[o * YSS + i];
        }
        for (int idx = t; idx < 32 * 32; idx += 256) {
            int o = idx >> 5, jw = idx & 31;
            const float* yr = &Ys[(32 + o) * YSS];
            float m0 = fmaxf(yr[2 * jw],      yr[2 * jw + 1]);
            float m1 = fmaxf(yr[64 + 2 * jw], yr[64 + 2 * jw + 1]);
            g_phi[((size_t)n * Dd + o) * Mm + bi * 32 + jw] = fmaxf(m0, m1);
        }
    } else {
        int vbase = (grp - 1) * 64;
        for (int idx = t; idx < 64 * 32; idx += 256) {
            int v = idx >> 5, jw = idx & 31;
            const float* yr = &Ys[v * YSS];
            float m0 = fmaxf(yr[2 * jw],      yr[2 * jw + 1]);
            float m1 = fmaxf(yr[64 + 2 * jw], yr[64 + 2 * jw + 1]);
            g_gp[((size_t)n * Dv + vbase + v) * Mm + bi * 32 + jw] =
                __float2bfloat16(fmaxf(m0, m1));
        }
    }
}

// ---------------------------------------------------------------------------
// Kernel 2: FUSED flash attention + out conv + residual.
// Energy: tf32 m16n8k8. P.V: bf16 m16n8k16 (P A-frags packed from E C-frags,
// zero shuffles). Out-conv: bf16 m16n8k16 straight from O C-frags (no smem O).
// grid (32 q-tiles, 8 batches), 256 threads = 8 warps x 16 q.
// ---------------------------------------------------------------------------
#define KB   64
#define PHS  72   // phi fp32 stride (floats)
#define GSH  72   // g bf16 stride (halfs); word stride 36 -> banks 4gq+tq
#define WSH  136  // out_w bf16 stride (halfs); word stride 68 -> banks 4gq+tq

__global__ void __launch_bounds__(256, 2) attn_fused_kernel(
    const float* __restrict__ x,
    const float* __restrict__ out_w,
    const float* __restrict__ out_b,
    const float* __restrict__ gamma,
    float* __restrict__ out)
{
    extern __shared__ float sm[];
    float* Phs = sm;                                        // 2 x 32 x 72 fp32
    __nv_bfloat16* Gsh = (__nv_bfloat16*)(sm + 2 * Dd * PHS); // 2 x 128 x 72 bf16
    __nv_bfloat16* Wsm = (__nv_bfloat16*)sm;                // phase3: 64 x 136 bf16

    const int n  = blockIdx.y;
    const int i0 = blockIdx.x * 128;
    const int t  = threadIdx.x;
    const int w  = t >> 5;
    const int lane = t & 31;
    const int qb = w * 16;
    const int gq = lane >> 2;
    const int tq = lane & 3;

    // Q A-fragments (persist)
    uint32_t qa[4][4];
    {
        const float* th = g_theta + ((size_t)n * Nn + i0 + qb) * Dd;
#pragma unroll
        for (int kc = 0; kc < 4; kc++) {
            qa[kc][0] = __float_as_uint(th[(gq    ) * Dd + kc * 8 + tq    ]);
            qa[kc][1] = __float_as_uint(th[(gq + 8) * Dd + kc * 8 + tq    ]);
            qa[kc][2] = __float_as_uint(th[(gq    ) * Dd + kc * 8 + tq + 4]);
            qa[kc][3] = __float_as_uint(th[(gq + 8) * Dd + kc * 8 + tq + 4]);
        }
    }

    auto issue = [&](int jb, int buf) {
        float* Pb = Phs + buf * Dd * PHS;
        __nv_bfloat16* Gb = Gsh + buf * Dv * GSH;
#pragma unroll
        for (int it = 0; it < 2; it++) {
            int idx = t + it * 256;                 // phi: 512 cp16
            int d = idx >> 4, j4 = (idx & 15) * 4;
            cp16(&Pb[d * PHS + j4], &g_phi[((size_t)n * Dd + d) * Mm + jb + j4]);
        }
#pragma unroll
        for (int it = 0; it < 4; it++) {
            int idx = t + it * 256;                 // g bf16: 1024 cp16 (8 halfs)
            int vv = idx >> 3, p8 = (idx & 7) * 8;
            cp16(&Gb[vv * GSH + p8], &g_gp[((size_t)n * Dv + vv) * Mm + jb + p8]);
        }
        cp_commit();
    };

    float oacc[16][4];
#pragma unroll
    for (int vt = 0; vt < 16; vt++)
#pragma unroll
        for (int c = 0; c < 4; c++) oacc[vt][c] = 0.f;

    float m0 = -1e30f, m1 = -1e30f, l0 = 0.f, l1 = 0.f;

    issue(0, 0);
    for (int kb = 0; kb < Mm / KB; kb++) {
        if (kb < Mm / KB - 1) { issue((kb + 1) * KB, (kb + 1) & 1); cp_wait<1>(); }
        else                  { cp_wait<0>(); }
        __syncthreads();
        const float* Pb = Phs + (kb & 1) * Dd * PHS;
        const uint32_t* Gw = (const uint32_t*)(Gsh + (kb & 1) * Dv * GSH);

        // ---- energy: tf32, E[16q x 64k] per warp ----
        float e[8][4];
#pragma unroll
        for (int nt = 0; nt < 8; nt++)
#pragma unroll
            for (int c = 0; c < 4; c++) e[nt][c] = 0.f;
#pragma unroll
        for (int kc = 0; kc < 4; kc++)
#pragma unroll
            for (int nt = 0; nt < 8; nt++) {
                uint32_t b0 = __float_as_uint(Pb[(kc * 8 + tq    ) * PHS + nt * 8 + gq]);
                uint32_t b1 = __float_as_uint(Pb[(kc * 8 + tq + 4) * PHS + nt * 8 + gq]);
                mma_tf32(e[nt], qa[kc], b0, b1);
            }

        // ---- online softmax ----
        float rm0 = m0, rm1 = m1;
#pragma unroll
        for (int nt = 0; nt < 8; nt++) {
            rm0 = fmaxf(rm0, fmaxf(e[nt][0], e[nt][1]));
            rm1 = fmaxf(rm1, fmaxf(e[nt][2], e[nt][3]));
        }
        rm0 = fmaxf(rm0, __shfl_xor_sync(0xffffffff, rm0, 1));
        rm0 = fmaxf(rm0, __shfl_xor_sync(0xffffffff, rm0, 2));
        rm1 = fmaxf(rm1, __shfl_xor_sync(0xffffffff, rm1, 1));
        rm1 = fmaxf(rm1, __shfl_xor_sync(0xffffffff, rm1, 2));
        float sc0 = __expf(m0 - rm0);
        float sc1 = __expf(m1 - rm1);
        m0 = rm0; m1 = rm1;

        float s0 = 0.f, s1 = 0.f;
#pragma unroll
        for (int nt = 0; nt < 8; nt++) {
            e[nt][0] = __expf(e[nt][0] - rm0);
            e[nt][1] = __expf(e[nt][1] - rm0);
            e[nt][2] = __expf(e[nt][2] - rm1);
            e[nt][3] = __expf(e[nt][3] - rm1);
            s0 += e[nt][0] + e[nt][1];
            s1 += e[nt][2] + e[nt][3];
        }
        s0 += __shfl_xor_sync(0xffffffff, s0, 1);
        s0 += __shfl_xor_sync(0xffffffff, s0, 2);
        s1 += __shfl_xor_sync(0xffffffff, s1, 1);
        s1 += __shfl_xor_sync(0xffffffff, s1, 2);
        l0 = l0 * sc0 + s0;
        l1 = l1 * sc1 + s1;

#pragma unroll
        for (int vt = 0; vt < 16; vt++) {
            oacc[vt][0] *= sc0; oacc[vt][1] *= sc0;
            oacc[vt][2] *= sc1; oacc[vt][3] *= sc1;
        }

        // ---- P.V: bf16 m16n8k16. A = packed E C-frags (no shuffles). ----
#pragma unroll
        for (int kc = 0; kc < 4; kc++) {
            uint32_t pa[4];
            pa[0] = pkbf(e[2*kc  ][0], e[2*kc  ][1]);
            pa[1] = pkbf(e[2*kc  ][2], e[2*kc  ][3]);
            pa[2] = pkbf(e[2*kc+1][0], e[2*kc+1][1]);
            pa[3] = pkbf(e[2*kc+1][2], e[2*kc+1][3]);
#pragma unroll
            for (int vt = 0; vt < 16; vt++) {
                uint32_t b0 = Gw[(vt * 8 + gq) * (GSH/2) + kc * 8 + tq    ];
                uint32_t b1 = Gw[(vt * 8 + gq) * (GSH/2) + kc * 8 + tq + 4];
                mma_bf16(oacc[vt], pa, b0, b1);
            }
        }
        __syncthreads();
    }

    // ---- phase 2: pack normalized O into bf16 A-frags (registers only) ----
    uint32_t oa[8][4];
    {
        const float inv0 = 1.f / l0;
        const float inv1 = 1.f / l1;
#pragma unroll
        for (int kc = 0; kc < 8; kc++) {
            oa[kc][0] = pkbf(oacc[2*kc  ][0] * inv0, oacc[2*kc  ][1] * inv0);
            oa[kc][1] = pkbf(oacc[2*kc  ][2] * inv1, oacc[2*kc  ][3] * inv1);
            oa[kc][2] = pkbf(oacc[2*kc+1][0] * inv0, oacc[2*kc+1][1] * inv0);
            oa[kc][3] = pkbf(oacc[2*kc+1][2] * inv1, oacc[2*kc+1][3] * inv1);
        }
    }

    // ---- phase 3: out conv (bf16), 4 passes of 64 channels ----
    const float gm = gamma[0];
    const uint32_t* Ww = (const uint32_t*)Wsm;

    for (int pass = 0; pass < 4; pass++) {
        const int cbase = pass * 64;

        // fill Wsm bf16 [64 c x 128 v] from fp32 out_w
#pragma unroll
        for (int it = 0; it < 8; it++) {
            int idx = t + it * 256;                  // 2048: 64 x 32 float4
            int r = idx >> 5, v4 = (idx & 31) * 4;
            float4 wv = *(const float4*)&out_w[(size_t)(cbase + r) * Dv + v4];
            uint2 p;
            p.x = pkbf(wv.x, wv.y);
            p.y = pkbf(wv.z, wv.w);
            *(uint2*)&Wsm[r * WSH + v4] = p;
        }
        __syncthreads();

        // C[16q x 64c] per warp: nt8 x kc8, A in regs
#pragma unroll
        for (int nt = 0; nt < 8; nt++) {
            float acc[4] = {0.f, 0.f, 0.f, 0.f};
#pragma unroll
            for (int kc = 0; kc < 8; kc++) {
                uint32_t b0 = Ww[(nt * 8 + gq) * (WSH/2) + kc * 8 + tq    ];
                uint32_t b1 = Ww[(nt * 8 + gq) * (WSH/2) + kc * 8 + tq + 4];
                mma_bf16(acc, oa[kc], b0, b1);
            }
            // epilogue: out[c][q] = gm*(acc + b[c]) + x[c][q]
            int c0 = cbase + nt * 8 + 2 * tq;
            int q0 = i0 + qb + gq;
            float bb0 = out_b[c0], bb1 = out_b[c0 + 1];
            size_t o00 = ((size_t)n * Cc + c0    ) * Nn + q0;
            size_t o10 = ((size_t)n * Cc + c0 + 1) * Nn + q0;
            out[o00]     = gm * (acc[0] + bb0) + x[o00];
            out[o10]     = gm * (acc[1] + bb1) + x[o10];
            out[o00 + 8] = gm * (acc[2] + bb0) + x[o00 + 8];
            out[o10 + 8] = gm * (acc[3] + bb1) + x[o10 + 8];
        }
        if (pass < 3) __syncthreads();
    }
}

// ---------------------------------------------------------------------------
extern "C" void kernel_launch(void* const* d_in, const int* in_sizes, int n_in,
                              void* d_out, int out_size)
{
    const float* x       = (const float*)d_in[0];
    const float* theta_w = (const float*)d_in[1];
    const float* theta_b = (const float*)d_in[2];
    const float* phi_w   = (const float*)d_in[3];
    const float* phi_b   = (const float*)d_in[4];
    const float* g_w     = (const float*)d_in[5];
    const float* g_b     = (const float*)d_in[6];
    const float* out_w   = (const float*)d_in[7];
    const float* out_b   = (const float*)d_in[8];
    const float* gamma   = (const float*)d_in[9];
    float* out = (float*)d_out;

    const int smem1 = 13312 * 4;                         // 53 KB
    // phase1: 2*32*72*4 + 2*128*72*2 = 18432 + 36864 = 55296 B; phase3 fits inside
    const int smem2 = 55296;

    cudaFuncSetAttribute(proj_mma_kernel,   cudaFuncAttributeMaxDynamicSharedMemorySize, smem1);
    cudaFuncSetAttribute(attn_fused_kernel, cudaFuncAttributeMaxDynamicSharedMemorySize, smem2);

    proj_mma_kernel<<<dim3(32, 3, Bn), 256, smem1>>>(x, theta_w, theta_b,
                                                     phi_w, phi_b, g_w, g_b);
    attn_fused_kernel<<<dim3(32, Bn), 256, smem2>>>(x, out_w, out_b, gamma, out);
}

// round 8
// speedup vs baseline: 1.6314x; 1.0200x over previous
#include <cuda_runtime.h>
#include <cuda_bf16.h>
#include <cstddef>
#include <cstdint>

#define Bn 8
#define Cc 256
#define Nn 4096      // 64*64 spatial
#define Mm 1024      // 32*32 pooled
#define Dd 32
#define Dv 128

// Scratch (device globals; no allocations allowed)
// g_phi:  (n, j, d) fp32, d permuted per 8-group [0,4,1,5,2,6,3,7]
// g_gp:   (n, v, j) bf16, j-words permuted per 16-j group (same pattern)
__device__ float          g_theta[Bn * Nn * Dd];   // (n, i, d) fp32
__device__ float          g_phi  [Bn * Mm * Dd];
__device__ __nv_bfloat16  g_gp   [Bn * Dv * Mm];

__device__ __forceinline__ void mma_tf32(float c[4], const uint32_t a[4],
                                         uint32_t b0, uint32_t b1) {
    asm volatile("mma.sync.aligned.m16n8k8.row.col.f32.tf32.tf32.f32 "
        "{%0,%1,%2,%3}, {%4,%5,%6,%7}, {%8,%9}, {%0,%1,%2,%3};"
        : "+f"(c[0]), "+f"(c[1]), "+f"(c[2]), "+f"(c[3])
        : "r"(a[0]), "r"(a[1]), "r"(a[2]), "r"(a[3]), "r"(b0), "r"(b1));
}
__device__ __forceinline__ void mma_bf16(float c[4], const uint32_t a[4],
                                         uint32_t b0, uint32_t b1) {
    asm volatile("mma.sync.aligned.m16n8k16.row.col.f32.bf16.bf16.f32 "
        "{%0,%1,%2,%3}, {%4,%5,%6,%7}, {%8,%9}, {%0,%1,%2,%3};"
        : "+f"(c[0]), "+f"(c[1]), "+f"(c[2]), "+f"(c[3])
        : "r"(a[0]), "r"(a[1]), "r"(a[2]), "r"(a[3]), "r"(b0), "r"(b1));
}
__device__ __forceinline__ uint32_t pkbf(float lo, float hi) {
    uint32_t r;
    asm("cvt.rn.bf16x2.f32 %0, %1, %2;" : "=r"(r) : "f"(hi), "f"(lo));
    return r;
}
__device__ __forceinline__ void cp16(void* dst_smem, const void* src) {
    uint32_t d = (uint32_t)__cvta_generic_to_shared(dst_smem);
    asm volatile("cp.async.cg.shared.global [%0], [%1], 16;\n" :: "r"(d), "l"(src));
}
__device__ __forceinline__ void cp_commit() {
    asm volatile("cp.async.commit_group;\n");
}
template<int N> __device__ __forceinline__ void cp_wait() {
    asm volatile("cp.async.wait_group %0;\n" :: "n"(N));
}
// position of element r within its 8-group under [0,4,1,5,2,6,3,7] order
__device__ __forceinline__ int perm8(int r) {
    return (r < 4) ? 2 * r : 2 * (r - 4) + 1;
}

// ---------------------------------------------------------------------------
// Kernel 1: fused projections + maxpool, tf32 MMA, cp.async double-buffered.
// Writes g_phi [j][d_perm] and g_gp [v][j_perm] (permuted for LDS.64 consumers).
// ---------------------------------------------------------------------------
#define WS  36
#define XSS 136
#define YSS 132

__global__ void __launch_bounds__(256, 3) proj_mma_kernel(
    const float* __restrict__ x,
    const float* __restrict__ theta_w, const float* __restrict__ theta_b,
    const float* __restrict__ phi_w,   const float* __restrict__ phi_b,
    const float* __restrict__ g_w,     const float* __restrict__ g_b)
{
    extern __shared__ float sm[];
    float* Ws = sm;                    // 2 x 64 x 36
    float* Xs = sm + 2 * 64 * WS;      // 2 x 32 x 136
    float* Ys = sm;                    // 64 x 132 (aliases pipeline)

    const int bi  = blockIdx.x;
    const int grp = blockIdx.y;
    const int n   = blockIdx.z;
    const int t   = threadIdx.x;
    const int w   = t >> 5, lane = t & 31;
    const int gq  = lane >> 2, tq = lane & 3;
    const int mrow = (w & 3) * 16;
    const int nc0  = (w >> 2) * 64;
    const int base = bi * 128;

    const float* xb = x + (size_t)n * Cc * Nn;

    auto issue = [&](int kc, int buf) {
        float* Wb = Ws + buf * 64 * WS;
        float* Xb = Xs + buf * 32 * XSS;
#pragma unroll
        for (int it = 0; it < 2; it++) {
            int idx = t + it * 256;
            int r = idx >> 3, kq = (idx & 7) * 4;
            const float* src;
            if (grp == 0) src = (r < 32) ? &theta_w[r * Cc + kc + kq]
                                         : &phi_w[(r - 32) * Cc + kc + kq];
            else          src = &g_w[((grp - 1) * 64 + r) * Cc + kc + kq];
            cp16(&Wb[r * WS + kq], src);
        }
#pragma unroll
        for (int it = 0; it < 4; it++) {
            int idx = t + it * 256;
            int k = idx >> 5, i4 = (idx & 31) * 4;
            cp16(&Xb[k * XSS + i4], &xb[(size_t)(kc + k) * Nn + base + i4]);
        }
        cp_commit();
    };

    float acc[8][4];
#pragma unroll
    for (int nt = 0; nt < 8; nt++)
#pragma unroll
        for (int c = 0; c < 4; c++) acc[nt][c] = 0.f;

    issue(0, 0);
    for (int c8 = 0; c8 < 8; c8++) {
        if (c8 < 7) { issue((c8 + 1) * 32, (c8 + 1) & 1); cp_wait<1>(); }
        else        { cp_wait<0>(); }
        __syncthreads();
        const float* Wb = Ws + (c8 & 1) * 64 * WS;
        const float* Xb = Xs + (c8 & 1) * 32 * XSS;
#pragma unroll
        for (int ks = 0; ks < 4; ks++) {
            uint32_t a[4];
            a[0] = __float_as_uint(Wb[(mrow + gq    ) * WS + ks * 8 + tq    ]);
            a[1] = __float_as_uint(Wb[(mrow + gq + 8) * WS + ks * 8 + tq    ]);
            a[2] = __float_as_uint(Wb[(mrow + gq    ) * WS + ks * 8 + tq + 4]);
            a[3] = __float_as_uint(Wb[(mrow + gq + 8) * WS + ks * 8 + tq + 4]);
#pragma unroll
            for (int nt = 0; nt < 8; nt++) {
                uint32_t b0 = __float_as_uint(Xb[(ks * 8 + tq    ) * XSS + nc0 + nt * 8 + gq]);
                uint32_t b1 = __float_as_uint(Xb[(ks * 8 + tq + 4) * XSS + nc0 + nt * 8 + gq]);
                mma_tf32(acc[nt], a, b0, b1);
            }
        }
        __syncthreads();
    }

    {
        int r0 = mrow + gq, r1 = mrow + gq + 8;
        float b0, b1;
        if (grp == 0) {
            b0 = (r0 < 32) ? theta_b[r0] : phi_b[r0 - 32];
            b1 = (r1 < 32) ? theta_b[r1] : phi_b[r1 - 32];
        } else {
            b0 = g_b[(grp - 1) * 64 + r0];
            b1 = g_b[(grp - 1) * 64 + r1];
        }
#pragma unroll
        for (int nt = 0; nt < 8; nt++) {
            int col = nc0 + nt * 8 + tq * 2;
            *(float2*)&Ys[r0 * YSS + col] = make_float2(acc[nt][0] + b0, acc[nt][1] + b0);
            *(float2*)&Ys[r1 * YSS + col] = make_float2(acc[nt][2] + b1, acc[nt][3] + b1);
        }
    }
    __syncthreads();

    if (grp == 0) {
        // theta rows 0..31 -> (n, i, d) unchanged
        for (int idx = t; idx < 32 * 128; idx += 256) {
            int o = idx & 31, i = idx >> 5;
            g_theta[((size_t)n * Nn + base + i) * Dd + o] = Ys[o * YSS + i];
        }
        // phi rows 32..63 -> maxpool -> (n, j, d_perm)
        for (int idx = t; idx < 32 * 32; idx += 256) {
            int o = idx & 31, jw = idx >> 5;    // lane varies d -> coalesced row write
            const float* yr = &Ys[(32 + o) * YSS];
            float m0 = fmaxf(yr[2 * jw],      yr[2 * jw + 1]);
            float m1 = fmaxf(yr[64 + 2 * jw], yr[64 + 2 * jw + 1]);
            int pos = (o & ~7) + perm8(o & 7);
            g_phi[((size_t)n * Mm + bi * 32 + jw) * Dd + pos] = fmaxf(m0, m1);
        }
    } else {
        int vbase = (grp - 1) * 64;
        // g -> maxpool -> (n, v, j_perm) bf16
        for (int idx = t; idx < 64 * 32; idx += 256) {
            int jw = idx & 31, v = idx >> 5;    // lane varies j -> coalesced
            const float* yr = &Ys[v * YSS];
            float m0 = fmaxf(yr[2 * jw],      yr[2 * jw + 1]);
            float m1 = fmaxf(yr[64 + 2 * jw], yr[64 + 2 * jw + 1]);
            int g16 = jw >> 4, wloc = (jw & 15) >> 1, lo = jw & 1;
            int pos = g16 * 16 + perm8(wloc) * 2 + lo;
            g_gp[((size_t)n * Dv + vbase + v) * Mm + bi * 32 + pos] =
                __float2bfloat16(fmaxf(m0, m1));
        }
    }
}

// ---------------------------------------------------------------------------
// Kernel 2: FUSED flash attention + out conv + residual.
// All B-fragment gathers are single LDS.64 (permuted layouts, stride 40 words).
// grid (32 q-tiles, 8 batches), 256 threads = 8 warps x 16 q.
// ---------------------------------------------------------------------------
#define KB    64
#define PHS2  40   // phi [j][d] stride in floats (32 data + 8 pad)
#define GSW   40   // g [v][j-words] stride in 32-bit words (32 data + 8 pad)
#define WSW   40   // out_w pane stride in words (64 data... 64+? see fill: 64 words data)
                   // NOTE: W rows have 64 words data; stride 72 words chosen below
#define WSTR  72   // W pane row stride in words (64 data + 8 pad)

__global__ void __launch_bounds__(256, 2) attn_fused_kernel(
    const float* __restrict__ x,
    const float* __restrict__ out_w,
    const float* __restrict__ out_b,
    const float* __restrict__ gamma,
    float* __restrict__ out)
{
    extern __shared__ float sm[];
    float* Phs = sm;                                          // 2 x 64 x 40 fp32
    uint32_t* Gsw = (uint32_t*)(sm + 2 * KB * PHS2);          // 2 x 128 x 40 words
    uint32_t* Wsw = (uint32_t*)sm;                            // phase3: 64 x 72 words

    const int n  = blockIdx.y;
    const int i0 = blockIdx.x * 128;
    const int t  = threadIdx.x;
    const int w  = t >> 5;
    const int lane = t & 31;
    const int qb = w * 16;
    const int gq = lane >> 2;
    const int tq = lane & 3;

    // Q A-fragments (persist)
    uint32_t qa[4][4];
    {
        const float* th = g_theta + ((size_t)n * Nn + i0 + qb) * Dd;
#pragma unroll
        for (int kc = 0; kc < 4; kc++) {
            qa[kc][0] = __float_as_uint(th[(gq    ) * Dd + kc * 8 + tq    ]);
            qa[kc][1] = __float_as_uint(th[(gq + 8) * Dd + kc * 8 + tq    ]);
            qa[kc][2] = __float_as_uint(th[(gq    ) * Dd + kc * 8 + tq + 4]);
            qa[kc][3] = __float_as_uint(th[(gq + 8) * Dd + kc * 8 + tq + 4]);
        }
    }

    auto issue = [&](int jb, int buf) {
        float* Pb = Phs + buf * KB * PHS2;
        uint32_t* Gb = Gsw + buf * Dv * GSW;
#pragma unroll
        for (int it = 0; it < 2; it++) {
            int idx = t + it * 256;                 // phi: 64 j x 32 d -> 512 cp16
            int j = idx >> 3, dq = (idx & 7) * 4;
            cp16(&Pb[j * PHS2 + dq], &g_phi[((size_t)n * Mm + jb + j) * Dd + dq]);
        }
#pragma unroll
        for (int it = 0; it < 4; it++) {
            int idx = t + it * 256;                 // g: 128 v x 64 halfs -> 1024 cp16
            int vv = idx >> 3, p8 = (idx & 7) * 8;
            cp16((__nv_bfloat16*)&Gb[vv * GSW] + p8,
                 &g_gp[((size_t)n * Dv + vv) * Mm + jb + p8]);
        }
        cp_commit();
    };

    float oacc[16][4];
#pragma unroll
    for (int vt = 0; vt < 16; vt++)
#pragma unroll
        for (int c = 0; c < 4; c++) oacc[vt][c] = 0.f;

    float m0 = -1e30f, m1 = -1e30f, l0 = 0.f, l1 = 0.f;

    issue(0, 0);
    for (int kb = 0; kb < Mm / KB; kb++) {
        if (kb < Mm / KB - 1) { issue((kb + 1) * KB, (kb + 1) & 1); cp_wait<1>(); }
        else                  { cp_wait<0>(); }
        __syncthreads();
        const float* Pb = Phs + (kb & 1) * KB * PHS2;
        const uint32_t* Gb = Gsw + (kb & 1) * Dv * GSW;

        // ---- energy: tf32, E[16q x 64k]; B pair via one LDS.64 ----
        float e[8][4];
#pragma unroll
        for (int nt = 0; nt < 8; nt++)
#pragma unroll
            for (int c = 0; c < 4; c++) e[nt][c] = 0.f;
#pragma unroll
        for (int kc = 0; kc < 4; kc++)
#pragma unroll
            for (int nt = 0; nt < 8; nt++) {
                float2 bb = *(const float2*)&Pb[(nt * 8 + gq) * PHS2 + kc * 8 + 2 * tq];
                mma_tf32(e[nt], qa[kc], __float_as_uint(bb.x), __float_as_uint(bb.y));
            }

        // ---- online softmax ----
        float rm0 = m0, rm1 = m1;
#pragma unroll
        for (int nt = 0; nt < 8; nt++) {
            rm0 = fmaxf(rm0, fmaxf(e[nt][0], e[nt][1]));
            rm1 = fmaxf(rm1, fmaxf(e[nt][2], e[nt][3]));
        }
        rm0 = fmaxf(rm0, __shfl_xor_sync(0xffffffff, rm0, 1));
        rm0 = fmaxf(rm0, __shfl_xor_sync(0xffffffff, rm0, 2));
        rm1 = fmaxf(rm1, __shfl_xor_sync(0xffffffff, rm1, 1));
        rm1 = fmaxf(rm1, __shfl_xor_sync(0xffffffff, rm1, 2));
        float sc0 = __expf(m0 - rm0);
        float sc1 = __expf(m1 - rm1);
        m0 = rm0; m1 = rm1;

        float s0 = 0.f, s1 = 0.f;
#pragma unroll
        for (int nt = 0; nt < 8; nt++) {
            e[nt][0] = __expf(e[nt][0] - rm0);
            e[nt][1] = __expf(e[nt][1] - rm0);
            e[nt][2] = __expf(e[nt][2] - rm1);
            e[nt][3] = __expf(e[nt][3] - rm1);
            s0 += e[nt][0] + e[nt][1];
            s1 += e[nt][2] + e[nt][3];
        }
        s0 += __shfl_xor_sync(0xffffffff, s0, 1);
        s0 += __shfl_xor_sync(0xffffffff, s0, 2);
        s1 += __shfl_xor_sync(0xffffffff, s1, 1);
        s1 += __shfl_xor_sync(0xffffffff, s1, 2);
        l0 = l0 * sc0 + s0;
        l1 = l1 * sc1 + s1;

#pragma unroll
        for (int vt = 0; vt < 16; vt++) {
            oacc[vt][0] *= sc0; oacc[vt][1] *= sc0;
            oacc[vt][2] *= sc1; oacc[vt][3] *= sc1;
        }

        // ---- P.V: bf16; B word-pair via one LDS.64 ----
#pragma unroll
        for (int kc = 0; kc < 4; kc++) {
            uint32_t pa[4];
            pa[0] = pkbf(e[2*kc  ][0], e[2*kc  ][1]);
            pa[1] = pkbf(e[2*kc  ][2], e[2*kc  ][3]);
            pa[2] = pkbf(e[2*kc+1][0], e[2*kc+1][1]);
            pa[3] = pkbf(e[2*kc+1][2], e[2*kc+1][3]);
#pragma unroll
            for (int vt = 0; vt < 16; vt++) {
                uint2 bb = *(const uint2*)&Gb[(vt * 8 + gq) * GSW + kc * 8 + 2 * tq];
                mma_bf16(oacc[vt], pa, bb.x, bb.y);
            }
        }
        __syncthreads();
    }

    // ---- phase 2: pack normalized O into bf16 A-frags (registers only) ----
    uint32_t oa[8][4];
    {
        const float inv0 = 1.f / l0;
        const float inv1 = 1.f / l1;
#pragma unroll
        for (int kc = 0; kc < 8; kc++) {
            oa[kc][0] = pkbf(oacc[2*kc  ][0] * inv0, oacc[2*kc  ][1] * inv0);
            oa[kc][1] = pkbf(oacc[2*kc  ][2] * inv1, oacc[2*kc  ][3] * inv1);
            oa[kc][2] = pkbf(oacc[2*kc+1][0] * inv0, oacc[2*kc+1][1] * inv0);
            oa[kc][3] = pkbf(oacc[2*kc+1][2] * inv1, oacc[2*kc+1][3] * inv1);
        }
    }

    // ---- phase 3: out conv (bf16), 4 passes of 64 channels ----
    const float gm = gamma[0];

    for (int pass = 0; pass < 4; pass++) {
        const int cbase = pass * 64;

        // fill W pane [64 c x 64 words], v-words permuted per 8-word group
#pragma unroll
        for (int it = 0; it < 8; it++) {
            int idx = t + it * 256;                  // 2048: 64 c x 32 float4
            int r = idx >> 5, v4 = (idx & 31) * 4;
            float4 wv = *(const float4*)&out_w[(size_t)(cbase + r) * Dv + v4];
            uint32_t w0 = pkbf(wv.x, wv.y);
            uint32_t w1 = pkbf(wv.z, wv.w);
            int wi0 = v4 >> 1, wi1 = wi0 + 1;
            Wsw[r * WSTR + (wi0 & ~7) + perm8(wi0 & 7)] = w0;
            Wsw[r * WSTR + (wi1 & ~7) + perm8(wi1 & 7)] = w1;
        }
        __syncthreads();

        // C[16q x 64c] per warp; B word-pair via one LDS.64
#pragma unroll
        for (int nt = 0; nt < 8; nt++) {
            float acc[4] = {0.f, 0.f, 0.f, 0.f};
#pragma unroll
            for (int kc = 0; kc < 8; kc++) {
                uint2 bb = *(const uint2*)&Wsw[(nt * 8 + gq) * WSTR + kc * 8 + 2 * tq];
                mma_bf16(acc, oa[kc], bb.x, bb.y);
            }
            int c0 = cbase + nt * 8 + 2 * tq;
            int q0 = i0 + qb + gq;
            float bb0 = out_b[c0], bb1 = out_b[c0 + 1];
            size_t o00 = ((size_t)n * Cc + c0    ) * Nn + q0;
            size_t o10 = ((size_t)n * Cc + c0 + 1) * Nn + q0;
            out[o00]     = gm * (acc[0] + bb0) + x[o00];
            out[o10]     = gm * (acc[1] + bb1) + x[o10];
            out[o00 + 8] = gm * (acc[2] + bb0) + x[o00 + 8];
            out[o10 + 8] = gm * (acc[3] + bb1) + x[o10 + 8];
        }
        if (pass < 3) __syncthreads();
    }
}

// ---------------------------------------------------------------------------
extern "C" void kernel_launch(void* const* d_in, const int* in_sizes, int n_in,
                              void* d_out, int out_size)
{
    const float* x       = (const float*)d_in[0];
    const float* theta_w = (const float*)d_in[1];
    const float* theta_b = (const float*)d_in[2];
    const float* phi_w   = (const float*)d_in[3];
    const float* phi_b   = (const float*)d_in[4];
    const float* g_w     = (const float*)d_in[5];
    const float* g_b     = (const float*)d_in[6];
    const float* out_w   = (const float*)d_in[7];
    const float* out_b   = (const float*)d_in[8];
    const float* gamma   = (const float*)d_in[9];
    float* out = (float*)d_out;

    const int smem1 = 13312 * 4;   // 53 KB
    // phase1: phi 2*64*40*4 = 20480 + G 2*128*40*4 = 40960 -> 61440 B
    // phase3: 64*72*4 = 18432 B (aliases)
    const int smem2 = 61440;

    cudaFuncSetAttribute(proj_mma_kernel,   cudaFuncAttributeMaxDynamicSharedMemorySize, smem1);
    cudaFuncSetAttribute(attn_fused_kernel, cudaFuncAttributeMaxDynamicSharedMemorySize, smem2);

    proj_mma_kernel<<<dim3(32, 3, Bn), 256, smem1>>>(x, theta_w, theta_b,
                                                     phi_w, phi_b, g_w, g_b);
    attn_fused_kernel<<<dim3(32, Bn), 256, smem2>>>(x, out_w, out_b, gamma, out);
}

// round 9
// speedup vs baseline: 1.8006x; 1.1037x over previous
#include <cuda_runtime.h>
#include <cuda_bf16.h>
#include <cstddef>
#include <cstdint>

#define Bn 8
#define Cc 256
#define Nn 4096      // 64*64 spatial
#define Mm 1024      // 32*32 pooled
#define Dd 32
#define Dv 128

// Scratch (device globals; no allocations allowed)
// g_phi:  (n, j, d) fp32, d permuted per 8-group [0,4,1,5,2,6,3,7]
// g_gp:   (n, v, j) bf16, j-words permuted per 16-j group (same pattern)
__device__ float          g_theta[Bn * Nn * Dd];   // (n, i, d) fp32
__device__ float          g_phi  [Bn * Mm * Dd];
__device__ __nv_bfloat16  g_gp   [Bn * Dv * Mm];

__device__ __forceinline__ void mma_tf32(float c[4], const uint32_t a[4],
                                         uint32_t b0, uint32_t b1) {
    asm volatile("mma.sync.aligned.m16n8k8.row.col.f32.tf32.tf32.f32 "
        "{%0,%1,%2,%3}, {%4,%5,%6,%7}, {%8,%9}, {%0,%1,%2,%3};"
        : "+f"(c[0]), "+f"(c[1]), "+f"(c[2]), "+f"(c[3])
        : "r"(a[0]), "r"(a[1]), "r"(a[2]), "r"(a[3]), "r"(b0), "r"(b1));
}
__device__ __forceinline__ void mma_bf16(float c[4], const uint32_t a[4],
                                         uint32_t b0, uint32_t b1) {
    asm volatile("mma.sync.aligned.m16n8k16.row.col.f32.bf16.bf16.f32 "
        "{%0,%1,%2,%3}, {%4,%5,%6,%7}, {%8,%9}, {%0,%1,%2,%3};"
        : "+f"(c[0]), "+f"(c[1]), "+f"(c[2]), "+f"(c[3])
        : "r"(a[0]), "r"(a[1]), "r"(a[2]), "r"(a[3]), "r"(b0), "r"(b1));
}
__device__ __forceinline__ uint32_t pkbf(float lo, float hi) {
    uint32_t r;
    asm("cvt.rn.bf16x2.f32 %0, %1, %2;" : "=r"(r) : "f"(hi), "f"(lo));
    return r;
}
__device__ __forceinline__ void cp16(void* dst_smem, const void* src) {
    uint32_t d = (uint32_t)__cvta_generic_to_shared(dst_smem);
    asm volatile("cp.async.cg.shared.global [%0], [%1], 16;\n" :: "r"(d), "l"(src));
}
__device__ __forceinline__ void cp_commit() {
    asm volatile("cp.async.commit_group;\n");
}
template<int N> __device__ __forceinline__ void cp_wait() {
    asm volatile("cp.async.wait_group %0;\n" :: "n"(N));
}
// position of element r within its 8-group under [0,4,1,5,2,6,3,7] order
__device__ __forceinline__ int perm8(int r) {
    return (r < 4) ? 2 * r : 2 * (r - 4) + 1;
}

// ---------------------------------------------------------------------------
// Kernel 1: fused projections + maxpool, tf32 MMA, cp.async double-buffered.
// Writes g_phi [j][d_perm] and g_gp [v][j_perm] (permuted for LDS.64 consumers).
// ---------------------------------------------------------------------------
#define WS  36
#define XSS 136
#define YSS 132

__global__ void __launch_bounds__(256, 3) proj_mma_kernel(
    const float* __restrict__ x,
    const float* __restrict__ theta_w, const float* __restrict__ theta_b,
    const float* __restrict__ phi_w,   const float* __restrict__ phi_b,
    const float* __restrict__ g_w,     const float* __restrict__ g_b)
{
    extern __shared__ float sm[];
    float* Ws = sm;                    // 2 x 64 x 36
    float* Xs = sm + 2 * 64 * WS;      // 2 x 32 x 136
    float* Ys = sm;                    // 64 x 132 (aliases pipeline)

    const int bi  = blockIdx.x;
    const int grp = blockIdx.y;
    const int n   = blockIdx.z;
    const int t   = threadIdx.x;
    const int w   = t >> 5, lane = t & 31;
    const int gq  = lane >> 2, tq = lane & 3;
    const int mrow = (w & 3) * 16;
    const int nc0  = (w >> 2) * 64;
    const int base = bi * 128;

    const float* xb = x + (size_t)n * Cc * Nn;

    auto issue = [&](int kc, int buf) {
        float* Wb = Ws + buf * 64 * WS;
        float* Xb = Xs + buf * 32 * XSS;
#pragma unroll
        for (int it = 0; it < 2; it++) {
            int idx = t + it * 256;
            int r = idx >> 3, kq = (idx & 7) * 4;
            const float* src;
            if (grp == 0) src = (r < 32) ? &theta_w[r * Cc + kc + kq]
                                         : &phi_w[(r - 32) * Cc + kc + kq];
            else          src = &g_w[((grp - 1) * 64 + r) * Cc + kc + kq];
            cp16(&Wb[r * WS + kq], src);
        }
#pragma unroll
        for (int it = 0; it < 4; it++) {
            int idx = t + it * 256;
            int k = idx >> 5, i4 = (idx & 31) * 4;
            cp16(&Xb[k * XSS + i4], &xb[(size_t)(kc + k) * Nn + base + i4]);
        }
        cp_commit();
    };

    float acc[8][4];
#pragma unroll
    for (int nt = 0; nt < 8; nt++)
#pragma unroll
        for (int c = 0; c < 4; c++) acc[nt][c] = 0.f;

    issue(0, 0);
    for (int c8 = 0; c8 < 8; c8++) {
        if (c8 < 7) { issue((c8 + 1) * 32, (c8 + 1) & 1); cp_wait<1>(); }
        else        { cp_wait<0>(); }
        __syncthreads();
        const float* Wb = Ws + (c8 & 1) * 64 * WS;
        const float* Xb = Xs + (c8 & 1) * 32 * XSS;
#pragma unroll
        for (int ks = 0; ks < 4; ks++) {
            uint32_t a[4];
            a[0] = __float_as_uint(Wb[(mrow + gq    ) * WS + ks * 8 + tq    ]);
            a[1] = __float_as_uint(Wb[(mrow + gq + 8) * WS + ks * 8 + tq    ]);
            a[2] = __float_as_uint(Wb[(mrow + gq    ) * WS + ks * 8 + tq + 4]);
            a[3] = __float_as_uint(Wb[(mrow + gq + 8) * WS + ks * 8 + tq + 4]);
#pragma unroll
            for (int nt = 0; nt < 8; nt++) {
                uint32_t b0 = __float_as_uint(Xb[(ks * 8 + tq    ) * XSS + nc0 + nt * 8 + gq]);
                uint32_t b1 = __float_as_uint(Xb[(ks * 8 + tq + 4) * XSS + nc0 + nt * 8 + gq]);
                mma_tf32(acc[nt], a, b0, b1);
            }
        }
        __syncthreads();
    }

    {
        int r0 = mrow + gq, r1 = mrow + gq + 8;
        float b0, b1;
        if (grp == 0) {
            b0 = (r0 < 32) ? theta_b[r0] : phi_b[r0 - 32];
            b1 = (r1 < 32) ? theta_b[r1] : phi_b[r1 - 32];
        } else {
            b0 = g_b[(grp - 1) * 64 + r0];
            b1 = g_b[(grp - 1) * 64 + r1];
        }
#pragma unroll
        for (int nt = 0; nt < 8; nt++) {
            int col = nc0 + nt * 8 + tq * 2;
            *(float2*)&Ys[r0 * YSS + col] = make_float2(acc[nt][0] + b0, acc[nt][1] + b0);
            *(float2*)&Ys[r1 * YSS + col] = make_float2(acc[nt][2] + b1, acc[nt][3] + b1);
        }
    }
    __syncthreads();

    if (grp == 0) {
        for (int idx = t; idx < 32 * 128; idx += 256) {
            int o = idx & 31, i = idx >> 5;
            g_theta[((size_t)n * Nn + base + i) * Dd + o] = Ys[o * YSS + i];
        }
        for (int idx = t; idx < 32 * 32; idx += 256) {
            int o = idx & 31, jw = idx >> 5;
            const float* yr = &Ys[(32 + o) * YSS];
            float m0 = fmaxf(yr[2 * jw],      yr[2 * jw + 1]);
            float m1 = fmaxf(yr[64 + 2 * jw], yr[64 + 2 * jw + 1]);
            int pos = (o & ~7) + perm8(o & 7);
            g_phi[((size_t)n * Mm + bi * 32 + jw) * Dd + pos] = fmaxf(m0, m1);
        }
    } else {
        int vbase = (grp - 1) * 64;
        for (int idx = t; idx < 64 * 32; idx += 256) {
            int jw = idx & 31, v = idx >> 5;
            const float* yr = &Ys[v * YSS];
            float m0 = fmaxf(yr[2 * jw],      yr[2 * jw + 1]);
            float m1 = fmaxf(yr[64 + 2 * jw], yr[64 + 2 * jw + 1]);
            int g16 = jw >> 4, wloc = (jw & 15) >> 1, lo = jw & 1;
            int pos = g16 * 16 + perm8(wloc) * 2 + lo;
            g_gp[((size_t)n * Dv + vbase + v) * Mm + bi * 32 + pos] =
                __float2bfloat16(fmaxf(m0, m1));
        }
    }
}

// ---------------------------------------------------------------------------
// Kernel 2: FUSED flash attention + out conv + residual.
// No-max softmax (range-bounded logits), per-pair fused energy/exp/PV,
// 3-stage cp.async pipeline with ONE barrier per iteration.
// grid (32 q-tiles, 8 batches), 256 threads = 8 warps x 16 q.
// ---------------------------------------------------------------------------
#define KB    64
#define PHS2  40   // phi [j][d] stride in floats
#define GSW   40   // g [v][j-words] stride in words
#define WSTR  72   // W pane row stride in words
#define NSTG  3    // pipeline stages

__global__ void __launch_bounds__(256, 2) attn_fused_kernel(
    const float* __restrict__ x,
    const float* __restrict__ out_w,
    const float* __restrict__ out_b,
    const float* __restrict__ gamma,
    float* __restrict__ out)
{
    extern __shared__ float sm[];
    float* Phs = sm;                                          // 3 x 64 x 40 fp32
    uint32_t* Gsw = (uint32_t*)(sm + NSTG * KB * PHS2);       // 3 x 128 x 40 words
    uint32_t* Wsw = (uint32_t*)sm;                            // phase3: 64 x 72 words

    const int n  = blockIdx.y;
    const int i0 = blockIdx.x * 128;
    const int t  = threadIdx.x;
    const int w  = t >> 5;
    const int lane = t & 31;
    const int qb = w * 16;
    const int gq = lane >> 2;
    const int tq = lane & 3;

    // Q A-fragments (persist)
    uint32_t qa[4][4];
    {
        const float* th = g_theta + ((size_t)n * Nn + i0 + qb) * Dd;
#pragma unroll
        for (int kc = 0; kc < 4; kc++) {
            qa[kc][0] = __float_as_uint(th[(gq    ) * Dd + kc * 8 + tq    ]);
            qa[kc][1] = __float_as_uint(th[(gq + 8) * Dd + kc * 8 + tq    ]);
            qa[kc][2] = __float_as_uint(th[(gq    ) * Dd + kc * 8 + tq + 4]);
            qa[kc][3] = __float_as_uint(th[(gq + 8) * Dd + kc * 8 + tq + 4]);
        }
    }

    auto issue = [&](int chunk) {
        int buf = chunk % NSTG;
        int jb = chunk * KB;
        float* Pb = Phs + buf * KB * PHS2;
        uint32_t* Gb = Gsw + buf * Dv * GSW;
#pragma unroll
        for (int it = 0; it < 2; it++) {
            int idx = t + it * 256;                 // phi: 64 j x 32 d -> 512 cp16
            int j = idx >> 3, dq = (idx & 7) * 4;
            cp16(&Pb[j * PHS2 + dq], &g_phi[((size_t)n * Mm + jb + j) * Dd + dq]);
        }
#pragma unroll
        for (int it = 0; it < 4; it++) {
            int idx = t + it * 256;                 // g: 128 v x 64 halfs -> 1024 cp16
            int vv = idx >> 3, p8 = (idx & 7) * 8;
            cp16((__nv_bfloat16*)&Gb[vv * GSW] + p8,
                 &g_gp[((size_t)n * Dv + vv) * Mm + jb + p8]);
        }
        cp_commit();
    };

    float oacc[16][4];
#pragma unroll
    for (int vt = 0; vt < 16; vt++)
#pragma unroll
        for (int c = 0; c < 4; c++) oacc[vt][c] = 0.f;

    float s0 = 0.f, s1 = 0.f;   // running exp-sum partials (reduced at end)

    issue(0); issue(1);
    for (int kb = 0; kb < Mm / KB; kb++) {
        if (kb < Mm / KB - 1) cp_wait<1>(); else cp_wait<0>();
        __syncthreads();                    // buffer kb visible; all warps past kb-1
        if (kb + 2 < Mm / KB) issue(kb + 2);

        const float* Pb = Phs + (kb % NSTG) * KB * PHS2;
        const uint32_t* Gb = Gsw + (kb % NSTG) * Dv * GSW;

        // per key-pair: energy (8 tf32 MMA) -> exp -> pack -> PV (16 bf16 MMA)
#pragma unroll
        for (int p = 0; p < 4; p++) {
            float ea[4] = {0.f, 0.f, 0.f, 0.f};
            float eb[4] = {0.f, 0.f, 0.f, 0.f};
#pragma unroll
            for (int kd = 0; kd < 4; kd++) {
                float2 ba = *(const float2*)&Pb[((2*p  ) * 8 + gq) * PHS2 + kd * 8 + 2 * tq];
                mma_tf32(ea, qa[kd], __float_as_uint(ba.x), __float_as_uint(ba.y));
            }
#pragma unroll
            for (int kd = 0; kd < 4; kd++) {
                float2 bb = *(const float2*)&Pb[((2*p+1) * 8 + gq) * PHS2 + kd * 8 + 2 * tq];
                mma_tf32(eb, qa[kd], __float_as_uint(bb.x), __float_as_uint(bb.y));
            }
            ea[0] = __expf(ea[0]); ea[1] = __expf(ea[1]);
            ea[2] = __expf(ea[2]); ea[3] = __expf(ea[3]);
            eb[0] = __expf(eb[0]); eb[1] = __expf(eb[1]);
            eb[2] = __expf(eb[2]); eb[3] = __expf(eb[3]);
            s0 += ea[0] + ea[1] + eb[0] + eb[1];
            s1 += ea[2] + ea[3] + eb[2] + eb[3];
            uint32_t pa[4];
            pa[0] = pkbf(ea[0], ea[1]);
            pa[1] = pkbf(ea[2], ea[3]);
            pa[2] = pkbf(eb[0], eb[1]);
            pa[3] = pkbf(eb[2], eb[3]);
#pragma unroll
            for (int vt = 0; vt < 16; vt++) {
                uint2 bb = *(const uint2*)&Gb[(vt * 8 + gq) * GSW + p * 8 + 2 * tq];
                mma_bf16(oacc[vt], pa, bb.x, bb.y);
            }
        }
    }

    // ---- exp-sum reduce (once) and O pack ----
    s0 += __shfl_xor_sync(0xffffffff, s0, 1);
    s0 += __shfl_xor_sync(0xffffffff, s0, 2);
    s1 += __shfl_xor_sync(0xffffffff, s1, 1);
    s1 += __shfl_xor_sync(0xffffffff, s1, 2);

    uint32_t oa[8][4];
    {
        const float inv0 = 1.f / s0;
        const float inv1 = 1.f / s1;
#pragma unroll
        for (int kc = 0; kc < 8; kc++) {
            oa[kc][0] = pkbf(oacc[2*kc  ][0] * inv0, oacc[2*kc  ][1] * inv0);
            oa[kc][1] = pkbf(oacc[2*kc  ][2] * inv1, oacc[2*kc  ][3] * inv1);
            oa[kc][2] = pkbf(oacc[2*kc+1][0] * inv0, oacc[2*kc+1][1] * inv0);
            oa[kc][3] = pkbf(oacc[2*kc+1][2] * inv1, oacc[2*kc+1][3] * inv1);
        }
    }
    __syncthreads();   // all warps done with pipeline smem before W pane aliasing

    // ---- phase 3: out conv (bf16), 4 passes of 64 channels ----
    const float gm = gamma[0];

    for (int pass = 0; pass < 4; pass++) {
        const int cbase = pass * 64;

        // fill W pane [64 c x 64 words], v-words permuted per 8-word group
#pragma unroll
        for (int it = 0; it < 8; it++) {
            int idx = t + it * 256;                  // 2048: 64 c x 32 float4
            int r = idx >> 5, v4 = (idx & 31) * 4;
            float4 wv = *(const float4*)&out_w[(size_t)(cbase + r) * Dv + v4];
            uint32_t w0 = pkbf(wv.x, wv.y);
            uint32_t w1 = pkbf(wv.z, wv.w);
            int wi0 = v4 >> 1, wi1 = wi0 + 1;
            Wsw[r * WSTR + (wi0 & ~7) + perm8(wi0 & 7)] = w0;
            Wsw[r * WSTR + (wi1 & ~7) + perm8(wi1 & 7)] = w1;
        }
        __syncthreads();

        // C[16q x 64c] per warp; B word-pair via one LDS.64
#pragma unroll
        for (int nt = 0; nt < 8; nt++) {
            float acc[4] = {0.f, 0.f, 0.f, 0.f};
#pragma unroll
            for (int kc = 0; kc < 8; kc++) {
                uint2 bb = *(const uint2*)&Wsw[(nt * 8 + gq) * WSTR + kc * 8 + 2 * tq];
                mma_bf16(acc, oa[kc], bb.x, bb.y);
            }
            int c0 = cbase + nt * 8 + 2 * tq;
            int q0 = i0 + qb + gq;
            float bb0 = out_b[c0], bb1 = out_b[c0 + 1];
            size_t o00 = ((size_t)n * Cc + c0    ) * Nn + q0;
            size_t o10 = ((size_t)n * Cc + c0 + 1) * Nn + q0;
            out[o00]     = gm * (acc[0] + bb0) + x[o00];
            out[o10]     = gm * (acc[1] + bb1) + x[o10];
            out[o00 + 8] = gm * (acc[2] + bb0) + x[o00 + 8];
            out[o10 + 8] = gm * (acc[3] + bb1) + x[o10 + 8];
        }
        if (pass < 3) __syncthreads();
    }
}

// ---------------------------------------------------------------------------
extern "C" void kernel_launch(void* const* d_in, const int* in_sizes, int n_in,
                              void* d_out, int out_size)
{
    const float* x       = (const float*)d_in[0];
    const float* theta_w = (const float*)d_in[1];
    const float* theta_b = (const float*)d_in[2];
    const float* phi_w   = (const float*)d_in[3];
    const float* phi_b   = (const float*)d_in[4];
    const float* g_w     = (const float*)d_in[5];
    const float* g_b     = (const float*)d_in[6];
    const float* out_w   = (const float*)d_in[7];
    const float* out_b   = (const float*)d_in[8];
    const float* gamma   = (const float*)d_in[9];
    float* out = (float*)d_out;

    const int smem1 = 13312 * 4;   // 53 KB
    // phase1: phi 3*64*40*4 = 30720 + G 3*128*40*4 = 61440 -> 92160 B
    // phase3: 64*72*4 = 18432 B (aliases)
    const int smem2 = 92160;

    cudaFuncSetAttribute(proj_mma_kernel,   cudaFuncAttributeMaxDynamicSharedMemorySize, smem1);
    cudaFuncSetAttribute(attn_fused_kernel, cudaFuncAttributeMaxDynamicSharedMemorySize, smem2);

    proj_mma_kernel<<<dim3(32, 3, Bn), 256, smem1>>>(x, theta_w, theta_b,
                                                     phi_w, phi_b, g_w, g_b);
    attn_fused_kernel<<<dim3(32, Bn), 256, smem2>>>(x, out_w, out_b, gamma, out);
}

// round 10
// speedup vs baseline: 1.8457x; 1.0251x over previous
#include <cuda_runtime.h>
#include <cuda_bf16.h>
#include <cstddef>
#include <cstdint>

#define Bn 8
#define Cc 256
#define Nn 4096      // 64*64 spatial
#define Mm 1024      // 32*32 pooled
#define Dd 32
#define Dv 128

// Scratch (device globals; no allocations allowed)
// g_phi:  (n, j, d) fp32, d permuted per 8-group [0,4,1,5,2,6,3,7]
// g_gp:   (n, v, j) bf16, j-words permuted per 16-j group (same pattern)
__device__ float          g_theta[Bn * Nn * Dd];   // (n, i, d) fp32
__device__ float          g_phi  [Bn * Mm * Dd];
__device__ __nv_bfloat16  g_gp   [Bn * Dv * Mm];

__device__ __forceinline__ void mma_tf32(float c[4], const uint32_t a[4],
                                         uint32_t b0, uint32_t b1) {
    asm volatile("mma.sync.aligned.m16n8k8.row.col.f32.tf32.tf32.f32 "
        "{%0,%1,%2,%3}, {%4,%5,%6,%7}, {%8,%9}, {%0,%1,%2,%3};"
        : "+f"(c[0]), "+f"(c[1]), "+f"(c[2]), "+f"(c[3])
        : "r"(a[0]), "r"(a[1]), "r"(a[2]), "r"(a[3]), "r"(b0), "r"(b1));
}
__device__ __forceinline__ void mma_bf16(float c[4], const uint32_t a[4],
                                         uint32_t b0, uint32_t b1) {
    asm volatile("mma.sync.aligned.m16n8k16.row.col.f32.bf16.bf16.f32 "
        "{%0,%1,%2,%3}, {%4,%5,%6,%7}, {%8,%9}, {%0,%1,%2,%3};"
        : "+f"(c[0]), "+f"(c[1]), "+f"(c[2]), "+f"(c[3])
        : "r"(a[0]), "r"(a[1]), "r"(a[2]), "r"(a[3]), "r"(b0), "r"(b1));
}
__device__ __forceinline__ uint32_t pkbf(float lo, float hi) {
    uint32_t r;
    asm("cvt.rn.bf16x2.f32 %0, %1, %2;" : "=r"(r) : "f"(hi), "f"(lo));
    return r;
}
__device__ __forceinline__ void cp16(void* dst_smem, const void* src) {
    uint32_t d = (uint32_t)__cvta_generic_to_shared(dst_smem);
    asm volatile("cp.async.cg.shared.global [%0], [%1], 16;\n" :: "r"(d), "l"(src));
}
__device__ __forceinline__ void cp_commit() {
    asm volatile("cp.async.commit_group;\n");
}
template<int N> __device__ __forceinline__ void cp_wait() {
    asm volatile("cp.async.wait_group %0;\n" :: "n"(N));
}
// position of element r within its 8-group under [0,4,1,5,2,6,3,7] order
__device__ __forceinline__ int perm8(int r) {
    return (r < 4) ? 2 * r : 2 * (r - 4) + 1;
}

// ---------------------------------------------------------------------------
// Kernel 1: fused projections + maxpool, tf32 MMA, cp.async double-buffered.
// Writes g_phi [j][d_perm] and g_gp [v][j_perm] (permuted for LDS.64 consumers).
// ---------------------------------------------------------------------------
#define WS  36
#define XSS 136
#define YSS 132

__global__ void __launch_bounds__(256, 3) proj_mma_kernel(
    const float* __restrict__ x,
    const float* __restrict__ theta_w, const float* __restrict__ theta_b,
    const float* __restrict__ phi_w,   const float* __restrict__ phi_b,
    const float* __restrict__ g_w,     const float* __restrict__ g_b)
{
    extern __shared__ float sm[];
    float* Ws = sm;                    // 2 x 64 x 36
    float* Xs = sm + 2 * 64 * WS;      // 2 x 32 x 136
    float* Ys = sm;                    // 64 x 132 (aliases pipeline)

    const int bi  = blockIdx.x;
    const int grp = blockIdx.y;
    const int n   = blockIdx.z;
    const int t   = threadIdx.x;
    const int w   = t >> 5, lane = t & 31;
    const int gq  = lane >> 2, tq = lane & 3;
    const int mrow = (w & 3) * 16;
    const int nc0  = (w >> 2) * 64;
    const int base = bi * 128;

    const float* xb = x + (size_t)n * Cc * Nn;

    auto issue = [&](int kc, int buf) {
        float* Wb = Ws + buf * 64 * WS;
        float* Xb = Xs + buf * 32 * XSS;
#pragma unroll
        for (int it = 0; it < 2; it++) {
            int idx = t + it * 256;
            int r = idx >> 3, kq = (idx & 7) * 4;
            const float* src;
            if (grp == 0) src = (r < 32) ? &theta_w[r * Cc + kc + kq]
                                         : &phi_w[(r - 32) * Cc + kc + kq];
            else          src = &g_w[((grp - 1) * 64 + r) * Cc + kc + kq];
            cp16(&Wb[r * WS + kq], src);
        }
#pragma unroll
        for (int it = 0; it < 4; it++) {
            int idx = t + it * 256;
            int k = idx >> 5, i4 = (idx & 31) * 4;
            cp16(&Xb[k * XSS + i4], &xb[(size_t)(kc + k) * Nn + base + i4]);
        }
        cp_commit();
    };

    float acc[8][4];
#pragma unroll
    for (int nt = 0; nt < 8; nt++)
#pragma unroll
        for (int c = 0; c < 4; c++) acc[nt][c] = 0.f;

    issue(0, 0);
    for (int c8 = 0; c8 < 8; c8++) {
        if (c8 < 7) { issue((c8 + 1) * 32, (c8 + 1) & 1); cp_wait<1>(); }
        else        { cp_wait<0>(); }
        __syncthreads();
        const float* Wb = Ws + (c8 & 1) * 64 * WS;
        const float* Xb = Xs + (c8 & 1) * 32 * XSS;
#pragma unroll
        for (int ks = 0; ks < 4; ks++) {
            uint32_t a[4];
            a[0] = __float_as_uint(Wb[(mrow + gq    ) * WS + ks * 8 + tq    ]);
            a[1] = __float_as_uint(Wb[(mrow + gq + 8) * WS + ks * 8 + tq    ]);
            a[2] = __float_as_uint(Wb[(mrow + gq    ) * WS + ks * 8 + tq + 4]);
            a[3] = __float_as_uint(Wb[(mrow + gq + 8) * WS + ks * 8 + tq + 4]);
#pragma unroll
            for (int nt = 0; nt < 8; nt++) {
                uint32_t b0 = __float_as_uint(Xb[(ks * 8 + tq    ) * XSS + nc0 + nt * 8 + gq]);
                uint32_t b1 = __float_as_uint(Xb[(ks * 8 + tq + 4) * XSS + nc0 + nt * 8 + gq]);
                mma_tf32(acc[nt], a, b0, b1);
            }
        }
        __syncthreads();
    }

    {
        int r0 = mrow + gq, r1 = mrow + gq + 8;
        float b0, b1;
        if (grp == 0) {
            b0 = (r0 < 32) ? theta_b[r0] : phi_b[r0 - 32];
            b1 = (r1 < 32) ? theta_b[r1] : phi_b[r1 - 32];
        } else {
            b0 = g_b[(grp - 1) * 64 + r0];
            b1 = g_b[(grp - 1) * 64 + r1];
        }
#pragma unroll
        for (int nt = 0; nt < 8; nt++) {
            int col = nc0 + nt * 8 + tq * 2;
            *(float2*)&Ys[r0 * YSS + col] = make_float2(acc[nt][0] + b0, acc[nt][1] + b0);
            *(float2*)&Ys[r1 * YSS + col] = make_float2(acc[nt][2] + b1, acc[nt][3] + b1);
        }
    }
    __syncthreads();

    if (grp == 0) {
        for (int idx = t; idx < 32 * 128; idx += 256) {
            int o = idx & 31, i = idx >> 5;
            g_theta[((size_t)n * Nn + base + i) * Dd + o] = Ys[o * YSS + i];
        }
        for (int idx = t; idx < 32 * 32; idx += 256) {
            int o = idx & 31, jw = idx >> 5;
            const float* yr = &Ys[(32 + o) * YSS];
            float m0 = fmaxf(yr[2 * jw],      yr[2 * jw + 1]);
            float m1 = fmaxf(yr[64 + 2 * jw], yr[64 + 2 * jw + 1]);
            int pos = (o & ~7) + perm8(o & 7);
            g_phi[((size_t)n * Mm + bi * 32 + jw) * Dd + pos] = fmaxf(m0, m1);
        }
    } else {
        int vbase = (grp - 1) * 64;
        for (int idx = t; idx < 64 * 32; idx += 256) {
            int jw = idx & 31, v = idx >> 5;
            const float* yr = &Ys[v * YSS];
            float m0 = fmaxf(yr[2 * jw],      yr[2 * jw + 1]);
            float m1 = fmaxf(yr[64 + 2 * jw], yr[64 + 2 * jw + 1]);
            int g16 = jw >> 4, wloc = (jw & 15) >> 1, lo = jw & 1;
            int pos = g16 * 16 + perm8(wloc) * 2 + lo;
            g_gp[((size_t)n * Dv + vbase + v) * Mm + bi * 32 + pos] =
                __float2bfloat16(fmaxf(m0, m1));
        }
    }
}

// ---------------------------------------------------------------------------
// Kernel 2: FUSED flash attention + out conv + residual.
// KB=128, 2-stage pipeline, ONE barrier per iter (8 main-loop barriers).
// Phase 3: full 256x128 W pane loaded once -> barrier-free c-passes.
// grid (32 q-tiles, 8 batches), 256 threads = 8 warps x 16 q.
// ---------------------------------------------------------------------------
#define KB    128
#define PHS2  40   // phi [j][d] stride in floats
#define GSW   72   // g [v][j-words] stride in words (64 data + 8 pad)
#define WSTR  72   // W pane row stride in words
#define NSTG  2    // pipeline stages

__global__ void __launch_bounds__(256, 2) attn_fused_kernel(
    const float* __restrict__ x,
    const float* __restrict__ out_w,
    const float* __restrict__ out_b,
    const float* __restrict__ gamma,
    float* __restrict__ out)
{
    extern __shared__ float sm[];
    float* Phs = sm;                                          // 2 x 128 x 40 fp32
    uint32_t* Gsw = (uint32_t*)(sm + NSTG * KB * PHS2);       // 2 x 128 x 72 words
    uint32_t* Wsw = (uint32_t*)sm;                            // phase3: 256 x 72 words

    const int n  = blockIdx.y;
    const int i0 = blockIdx.x * 128;
    const int t  = threadIdx.x;
    const int w  = t >> 5;
    const int lane = t & 31;
    const int qb = w * 16;
    const int gq = lane >> 2;
    const int tq = lane & 3;

    // Q A-fragments (persist)
    uint32_t qa[4][4];
    {
        const float* th = g_theta + ((size_t)n * Nn + i0 + qb) * Dd;
#pragma unroll
        for (int kc = 0; kc < 4; kc++) {
            qa[kc][0] = __float_as_uint(th[(gq    ) * Dd + kc * 8 + tq    ]);
            qa[kc][1] = __float_as_uint(th[(gq + 8) * Dd + kc * 8 + tq    ]);
            qa[kc][2] = __float_as_uint(th[(gq    ) * Dd + kc * 8 + tq + 4]);
            qa[kc][3] = __float_as_uint(th[(gq + 8) * Dd + kc * 8 + tq + 4]);
        }
    }

    auto issue = [&](int chunk) {
        int buf = chunk & 1;
        int jb = chunk * KB;
        float* Pb = Phs + buf * KB * PHS2;
        uint32_t* Gb = Gsw + buf * Dv * GSW;
#pragma unroll
        for (int it = 0; it < 4; it++) {
            int idx = t + it * 256;                 // phi: 128 j x 32 d -> 1024 cp16
            int j = idx >> 3, dq = (idx & 7) * 4;
            cp16(&Pb[j * PHS2 + dq], &g_phi[((size_t)n * Mm + jb + j) * Dd + dq]);
        }
#pragma unroll
        for (int it = 0; it < 8; it++) {
            int idx = t + it * 256;                 // g: 128 v x 128 halfs -> 2048 cp16
            int vv = idx >> 4, p8 = (idx & 15) * 8;
            cp16((__nv_bfloat16*)&Gb[vv * GSW] + p8,
                 &g_gp[((size_t)n * Dv + vv) * Mm + jb + p8]);
        }
        cp_commit();
    };

    float oacc[16][4];
#pragma unroll
    for (int vt = 0; vt < 16; vt++)
#pragma unroll
        for (int c = 0; c < 4; c++) oacc[vt][c] = 0.f;

    float s0 = 0.f, s1 = 0.f;   // running exp-sum partials (reduced at end)

    issue(0);
    for (int kb = 0; kb < Mm / KB; kb++) {
        cp_wait<0>();                       // group kb complete
        __syncthreads();                    // all warps past consume of kb-1
        if (kb + 1 < Mm / KB) issue(kb + 1);

        const float* Pb = Phs + (kb & 1) * KB * PHS2;
        const uint32_t* Gb = Gsw + (kb & 1) * Dv * GSW;

        // per key-pair p (16 keys): energy (8 tf32 MMA) -> exp -> pack -> PV (16 bf16 MMA)
#pragma unroll
        for (int p = 0; p < 8; p++) {
            float ea[4] = {0.f, 0.f, 0.f, 0.f};
            float eb[4] = {0.f, 0.f, 0.f, 0.f};
#pragma unroll
            for (int kd = 0; kd < 4; kd++) {
                float2 ba = *(const float2*)&Pb[((2*p  ) * 8 + gq) * PHS2 + kd * 8 + 2 * tq];
                mma_tf32(ea, qa[kd], __float_as_uint(ba.x), __float_as_uint(ba.y));
            }
#pragma unroll
            for (int kd = 0; kd < 4; kd++) {
                float2 bb = *(const float2*)&Pb[((2*p+1) * 8 + gq) * PHS2 + kd * 8 + 2 * tq];
                mma_tf32(eb, qa[kd], __float_as_uint(bb.x), __float_as_uint(bb.y));
            }
            ea[0] = __expf(ea[0]); ea[1] = __expf(ea[1]);
            ea[2] = __expf(ea[2]); ea[3] = __expf(ea[3]);
            eb[0] = __expf(eb[0]); eb[1] = __expf(eb[1]);
            eb[2] = __expf(eb[2]); eb[3] = __expf(eb[3]);
            s0 += ea[0] + ea[1] + eb[0] + eb[1];
            s1 += ea[2] + ea[3] + eb[2] + eb[3];
            uint32_t pa[4];
            pa[0] = pkbf(ea[0], ea[1]);
            pa[1] = pkbf(ea[2], ea[3]);
            pa[2] = pkbf(eb[0], eb[1]);
            pa[3] = pkbf(eb[2], eb[3]);
#pragma unroll
            for (int vt = 0; vt < 16; vt++) {
                uint2 bb = *(const uint2*)&Gb[(vt * 8 + gq) * GSW + p * 8 + 2 * tq];
                mma_bf16(oacc[vt], pa, bb.x, bb.y);
            }
        }
    }

    // ---- exp-sum reduce (once) and O pack ----
    s0 += __shfl_xor_sync(0xffffffff, s0, 1);
    s0 += __shfl_xor_sync(0xffffffff, s0, 2);
    s1 += __shfl_xor_sync(0xffffffff, s1, 1);
    s1 += __shfl_xor_sync(0xffffffff, s1, 2);

    uint32_t oa[8][4];
    {
        const float inv0 = 1.f / s0;
        const float inv1 = 1.f / s1;
#pragma unroll
        for (int kc = 0; kc < 8; kc++) {
            oa[kc][0] = pkbf(oacc[2*kc  ][0] * inv0, oacc[2*kc  ][1] * inv0);
            oa[kc][1] = pkbf(oacc[2*kc  ][2] * inv1, oacc[2*kc  ][3] * inv1);
            oa[kc][2] = pkbf(oacc[2*kc+1][0] * inv0, oacc[2*kc+1][1] * inv0);
            oa[kc][3] = pkbf(oacc[2*kc+1][2] * inv1, oacc[2*kc+1][3] * inv1);
        }
    }
    __syncthreads();   // all warps done with pipeline smem before W pane aliasing

    // ---- phase 3: out conv (bf16). Full W pane [256 c x 64 words] loaded once.
    const float gm = gamma[0];

#pragma unroll
    for (int it = 0; it < 32; it++) {
        int idx = t + it * 256;                  // 8192: 256 c x 32 float4
        int r = idx >> 5, v4 = (idx & 31) * 4;
        float4 wv = *(const float4*)&out_w[(size_t)r * Dv + v4];
        uint32_t w0 = pkbf(wv.x, wv.y);
        uint32_t w1 = pkbf(wv.z, wv.w);
        int wi0 = v4 >> 1, wi1 = wi0 + 1;
        Wsw[r * WSTR + (wi0 & ~7) + perm8(wi0 & 7)] = w0;
        Wsw[r * WSTR + (wi1 & ~7) + perm8(wi1 & 7)] = w1;
    }
    __syncthreads();

#pragma unroll
    for (int pass = 0; pass < 4; pass++) {
        const int cbase = pass * 64;
#pragma unroll
        for (int nt = 0; nt < 8; nt++) {
            float acc[4] = {0.f, 0.f, 0.f, 0.f};
#pragma unroll
            for (int kc = 0; kc < 8; kc++) {
                uint2 bb = *(const uint2*)&Wsw[(cbase + nt * 8 + gq) * WSTR + kc * 8 + 2 * tq];
                mma_bf16(acc, oa[kc], bb.x, bb.y);
            }
            int c0 = cbase + nt * 8 + 2 * tq;
            int q0 = i0 + qb + gq;
            float bb0 = out_b[c0], bb1 = out_b[c0 + 1];
            size_t o00 = ((size_t)n * Cc + c0    ) * Nn + q0;
            size_t o10 = ((size_t)n * Cc + c0 + 1) * Nn + q0;
            out[o00]     = gm * (acc[0] + bb0) + x[o00];
            out[o10]     = gm * (acc[1] + bb1) + x[o10];
            out[o00 + 8] = gm * (acc[2] + bb0) + x[o00 + 8];
            out[o10 + 8] = gm * (acc[3] + bb1) + x[o10 + 8];
        }
    }
}

// ---------------------------------------------------------------------------
extern "C" void kernel_launch(void* const* d_in, const int* in_sizes, int n_in,
                              void* d_out, int out_size)
{
    const float* x       = (const float*)d_in[0];
    const float* theta_w = (const float*)d_in[1];
    const float* theta_b = (const float*)d_in[2];
    const float* phi_w   = (const float*)d_in[3];
    const float* phi_b   = (const float*)d_in[4];
    const float* g_w     = (const float*)d_in[5];
    const float* g_b     = (const float*)d_in[6];
    const float* out_w   = (const float*)d_in[7];
    const float* out_b   = (const float*)d_in[8];
    const float* gamma   = (const float*)d_in[9];
    float* out = (float*)d_out;

    const int smem1 = 13312 * 4;   // 53 KB
    // phase1: phi 2*128*40*4 = 40960 + G 2*128*72*4 = 73728 -> 114688 B (112 KB)
    // phase3: W pane 256*72*4 = 73728 B (aliases)
    const int smem2 = 114688;

    cudaFuncSetAttribute(proj_mma_kernel,   cudaFuncAttributeMaxDynamicSharedMemorySize, smem1);
    cudaFuncSetAttribute(attn_fused_kernel, cudaFuncAttributeMaxDynamicSharedMemorySize, smem2);

    proj_mma_kernel<<<dim3(32, 3, Bn), 256, smem1>>>(x, theta_w, theta_b,
                                                     phi_w, phi_b, g_w, g_b);
    attn_fused_kernel<<<dim3(32, Bn), 256, smem2>>>(x, out_w, out_b, gamma, out);
}